// round 2
// baseline (speedup 1.0000x reference)
#include <cuda_runtime.h>
#include <math.h>

#define NROI 512
#define NCH 512
#define HF 37
#define WF 50
#define NCLS 11
#define POOLDIM 25088   // NCH * 7 * 7
#define FCDIM 4096

// ---------------- scratch (device globals; no allocation allowed) ----------
__device__ float g_pool[(size_t)NROI * POOLDIM];   // 51.4 MB
__device__ float g_fc1[(size_t)NROI * FCDIM];
__device__ float g_fc7[(size_t)NROI * FCDIM];
__device__ float g_ls[NROI * 55];                  // 44 loc + 11 score per roi
__device__ float g_bbox[NROI * 44];
__device__ float g_prob[NROI * 11];

__device__ __forceinline__ float neg_inf() { return __int_as_float(0xff800000); }
__device__ __forceinline__ float pos_inf() { return __int_as_float(0x7f800000); }

// ---------------- 1. ROI max-pool ------------------------------------------
// NOTE: XLA rewrites x/7 -> x * fl32(1/7). fl32(1/7) = 0x3E124925 is slightly
// ABOVE 1/7, so ceil() at exact multiples of 7 can bump by +1 depending on the
// ulp at that magnitude. Reproduce bit-exactly with __fmul_rn.
__global__ void roipool_kernel(const float* __restrict__ feat,
                               const float* __restrict__ rois,
                               const int* __restrict__ roi_idx) {
    int r = blockIdx.x;
    __shared__ int hs[7], he[7], ws[7], we[7];
    if (threadIdx.x == 0) {
        const float RECIP7 = 1.0f / 7.0f;   // compile-time fp32 reciprocal
        // rois stored (y1,x1,y2,x2); reference swaps to (x1,y1,x2,y2)
        float y1 = rois[r * 4 + 0], x1 = rois[r * 4 + 1];
        float y2 = rois[r * 4 + 2], x2 = rois[r * 4 + 3];
        float sw = rintf(x1 * 0.0625f);
        float ew = rintf(x2 * 0.0625f);
        float sh = rintf(y1 * 0.0625f);
        float eh = rintf(y2 * 0.0625f);
        float rw = fmaxf(ew - sw + 1.0f, 1.0f);
        float rh = fmaxf(eh - sh + 1.0f, 1.0f);
        #pragma unroll
        for (int p = 0; p < 7; p++) {
            float fp = (float)p;
            float h0 = floorf(__fmul_rn(fp * rh, RECIP7)) + sh;
            float h1 = ceilf(__fmul_rn((fp + 1.0f) * rh, RECIP7)) + sh;
            float w0 = floorf(__fmul_rn(fp * rw, RECIP7)) + sw;
            float w1 = ceilf(__fmul_rn((fp + 1.0f) * rw, RECIP7)) + sw;
            hs[p] = (int)fminf(fmaxf(h0, 0.0f), (float)HF);
            he[p] = (int)fminf(fmaxf(h1, 0.0f), (float)HF);
            ws[p] = (int)fminf(fmaxf(w0, 0.0f), (float)WF);
            we[p] = (int)fminf(fmaxf(w1, 0.0f), (float)WF);
        }
    }
    __syncthreads();
    int b = roi_idx[r];
    const float* f = feat + (size_t)b * NCH * HF * WF;
    for (int idx = threadIdx.x; idx < POOLDIM; idx += blockDim.x) {
        int c = idx / 49;
        int rem = idx - c * 49;
        int ph = rem / 7, pw = rem - (rem / 7) * 7;
        int h0 = hs[ph], h1 = he[ph], w0 = ws[pw], w1 = we[pw];
        float m = 0.0f;
        if (h1 > h0 && w1 > w0) {
            m = neg_inf();
            const float* fc_ = f + (size_t)c * (HF * WF);
            for (int y = h0; y < h1; y++)
                for (int x = w0; x < w1; x++)
                    m = fmaxf(m, fc_[y * WF + x]);
        }
        g_pool[(size_t)r * POOLDIM + idx] = m;
    }
}

// ---------------- 2. SGEMM 128x128x8, C = relu?(A*B + bias) ----------------
// A: MxK row-major, B: KxN row-major. M,N multiples of 128; K multiple of 8.
template <bool RELU>
__global__ void __launch_bounds__(256, 1)
sgemm_kernel(const float* __restrict__ A, const float* __restrict__ B,
             const float* __restrict__ bias, float* __restrict__ Cout,
             int M, int N, int K) {
    __shared__ float As[8][128];
    __shared__ float Bs[8][128];
    int t = threadIdx.x;
    int m0 = blockIdx.y * 128;
    int n0 = blockIdx.x * 128;
    int aRow = t >> 1;
    int aCol = (t & 1) * 4;
    int bRow = t >> 5;
    int bCol = (t & 31) * 4;
    int ty = t >> 4, tx = t & 15;

    float acc[8][8];
    #pragma unroll
    for (int i = 0; i < 8; i++)
        #pragma unroll
        for (int j = 0; j < 8; j++) acc[i][j] = 0.0f;

    for (int k0 = 0; k0 < K; k0 += 8) {
        float4 av = *(const float4*)(A + (size_t)(m0 + aRow) * K + k0 + aCol);
        As[aCol + 0][aRow] = av.x;
        As[aCol + 1][aRow] = av.y;
        As[aCol + 2][aRow] = av.z;
        As[aCol + 3][aRow] = av.w;
        float4 bv = *(const float4*)(B + (size_t)(k0 + bRow) * N + n0 + bCol);
        *(float4*)&Bs[bRow][bCol] = bv;
        __syncthreads();
        #pragma unroll
        for (int kk = 0; kk < 8; kk++) {
            float ra[8], rb[8];
            #pragma unroll
            for (int i = 0; i < 8; i++) ra[i] = As[kk][ty * 8 + i];
            #pragma unroll
            for (int j = 0; j < 8; j++) rb[j] = Bs[kk][tx * 8 + j];
            #pragma unroll
            for (int i = 0; i < 8; i++)
                #pragma unroll
                for (int j = 0; j < 8; j++)
                    acc[i][j] = fmaf(ra[i], rb[j], acc[i][j]);
        }
        __syncthreads();
    }
    #pragma unroll
    for (int i = 0; i < 8; i++) {
        int m = m0 + ty * 8 + i;
        #pragma unroll
        for (int j = 0; j < 8; j++) {
            int n = n0 + tx * 8 + j;
            float v = acc[i][j] + bias[n];
            if (RELU) v = fmaxf(v, 0.0f);
            Cout[(size_t)m * N + n] = v;
        }
    }
}

// ---------------- 3. loc + score heads (N=44 and N=11, K=4096) -------------
__global__ void head_kernel(const float* __restrict__ Wloc, const float* __restrict__ bloc,
                            const float* __restrict__ Wsc, const float* __restrict__ bsc) {
    int r = blockIdx.x;
    __shared__ float row[FCDIM];
    for (int i = threadIdx.x; i < FCDIM; i += blockDim.x)
        row[i] = g_fc7[(size_t)r * FCDIM + i];
    __syncthreads();
    int warp = threadIdx.x >> 5, lane = threadIdx.x & 31;
    for (int n = warp; n < 55; n += 8) {
        const float* W;
        float bb;
        int ncol, col;
        if (n < 44) { W = Wloc; bb = bloc[n]; ncol = 44; col = n; }
        else        { W = Wsc;  bb = bsc[n - 44]; ncol = 11; col = n - 44; }
        float s = 0.0f;
        for (int k = lane; k < FCDIM; k += 32)
            s = fmaf(row[k], W[(size_t)k * ncol + col], s);
        #pragma unroll
        for (int o = 16; o > 0; o >>= 1) s += __shfl_xor_sync(0xffffffffu, s, o);
        if (lane == 0) g_ls[r * 55 + n] = s + bb;
    }
}

// ---------------- 4. bbox decode + clip + softmax ---------------------------
__global__ void post_kernel(const float* __restrict__ rois, float* __restrict__ out) {
    int r = blockIdx.x * blockDim.x + threadIdx.x;
    if (r >= NROI) return;
    float y1 = rois[r * 4 + 0], x1 = rois[r * 4 + 1];
    float y2 = rois[r * 4 + 2], x2 = rois[r * 4 + 3];
    float sh_ = y2 - y1, sw_ = x2 - x1;
    float cy = y1 + 0.5f * sh_, cx = x1 + 0.5f * sw_;
    #pragma unroll
    for (int c = 0; c < NCLS; c++) {
        float dy = g_ls[r * 55 + c * 4 + 0] * 0.1f;
        float dx = g_ls[r * 55 + c * 4 + 1] * 0.1f;
        float dh = g_ls[r * 55 + c * 4 + 2] * 0.2f;
        float dw = g_ls[r * 55 + c * 4 + 3] * 0.2f;
        float ncy = dy * sh_ + cy;
        float ncx = dx * sw_ + cx;
        float nh = expf(dh) * sh_;
        float nw = expf(dw) * sw_;
        float by1 = fminf(fmaxf(ncy - 0.5f * nh, 0.0f), 600.0f);
        float bx1 = fminf(fmaxf(ncx - 0.5f * nw, 0.0f), 800.0f);
        float by2 = fminf(fmaxf(ncy + 0.5f * nh, 0.0f), 600.0f);
        float bx2 = fminf(fmaxf(ncx + 0.5f * nw, 0.0f), 800.0f);
        g_bbox[r * 44 + c * 4 + 0] = by1;
        g_bbox[r * 44 + c * 4 + 1] = bx1;
        g_bbox[r * 44 + c * 4 + 2] = by2;
        g_bbox[r * 44 + c * 4 + 3] = bx2;
        out[r * 44 + c * 4 + 0] = by1;
        out[r * 44 + c * 4 + 1] = bx1;
        out[r * 44 + c * 4 + 2] = by2;
        out[r * 44 + c * 4 + 3] = bx2;
    }
    // softmax over 11 scores
    float sc[NCLS];
    float mx = neg_inf();
    #pragma unroll
    for (int c = 0; c < NCLS; c++) {
        sc[c] = g_ls[r * 55 + 44 + c];
        mx = fmaxf(mx, sc[c]);
    }
    float sum = 0.0f;
    #pragma unroll
    for (int c = 0; c < NCLS; c++) { sc[c] = expf(sc[c] - mx); sum += sc[c]; }
    #pragma unroll
    for (int c = 0; c < NCLS; c++) {
        float p = sc[c] / sum;
        g_prob[r * 11 + c] = p;
        out[NROI * 44 + r * 11 + c] = p;
    }
}

// ---------------- 5. per-class NMS ------------------------------------------
__global__ void __launch_bounds__(512) nms_kernel(float* __restrict__ out) {
    int cls = blockIdx.x + 1;                 // classes 1..10
    int j = threadIdx.x;                      // 0..511
    __shared__ float key[NROI];
    __shared__ int order[NROI];
    __shared__ float4 sb[NROI];
    __shared__ unsigned char keep[NROI];

    float s = g_prob[j * 11 + cls];
    bool valid = s > 0.05f;
    float kj = valid ? -s : pos_inf();
    key[j] = kj;
    __syncthreads();
    // stable ascending argsort via rank counting
    int rank = 0;
    for (int i = 0; i < NROI; i++) {
        float ki = key[i];
        rank += (ki < kj) || (ki == kj && i < j);
    }
    order[rank] = j;
    __syncthreads();
    int src = order[j];
    float4 box = *(const float4*)&g_bbox[src * 44 + cls * 4]; // (y1,x1,y2,x2)
    sb[j] = box;
    keep[j] = (g_prob[src * 11 + cls] > 0.05f) ? 1 : 0;
    __syncthreads();

    float areaJ = (box.z - box.x) * (box.w - box.y);
    for (int i = 0; i < NROI - 1; i++) {
        if (keep[i] && j > i && keep[j]) {
            float4 bi = sb[i];
            float ty_ = fmaxf(box.x, bi.x);
            float tx_ = fmaxf(box.y, bi.y);
            float by_ = fminf(box.z, bi.z);
            float bx_ = fminf(box.w, bi.w);
            float ih = fmaxf(by_ - ty_, 0.0f);
            float iw = fmaxf(bx_ - tx_, 0.0f);
            float inter = ih * iw;
            float areaI = (bi.z - bi.x) * (bi.w - bi.y);
            float iou = inter / (areaJ + areaI - inter);
            if (iou > 0.3f) keep[j] = 0;   // NaN compares false, matching JAX
        }
        __syncthreads();
    }
    out[NROI * 44 + NROI * 11 + blockIdx.x * NROI + src] = keep[j] ? 1.0f : 0.0f;
}

// ---------------- launch ----------------------------------------------------
extern "C" void kernel_launch(void* const* d_in, const int* in_sizes, int n_in,
                              void* d_out, int out_size) {
    (void)in_sizes; (void)n_in; (void)out_size;
    const float* h    = (const float*)d_in[0];
    const float* rois = (const float*)d_in[1];
    const int*   ridx = (const int*)d_in[2];
    const float* W1   = (const float*)d_in[3];
    const float* b1   = (const float*)d_in[4];
    const float* W2   = (const float*)d_in[5];
    const float* b2   = (const float*)d_in[6];
    const float* Wloc = (const float*)d_in[7];
    const float* bloc = (const float*)d_in[8];
    const float* Wsc  = (const float*)d_in[9];
    const float* bsc  = (const float*)d_in[10];
    float* out = (float*)d_out;

    void *p_pool, *p_fc1, *p_fc7;
    cudaGetSymbolAddress(&p_pool, g_pool);
    cudaGetSymbolAddress(&p_fc1, g_fc1);
    cudaGetSymbolAddress(&p_fc7, g_fc7);

    roipool_kernel<<<NROI, 256>>>(h, rois, ridx);

    dim3 grid1(FCDIM / 128, NROI / 128);
    sgemm_kernel<true><<<grid1, 256>>>((const float*)p_pool, W1, b1, (float*)p_fc1,
                                       NROI, FCDIM, POOLDIM);
    dim3 grid2(FCDIM / 128, NROI / 128);
    sgemm_kernel<true><<<grid2, 256>>>((const float*)p_fc1, W2, b2, (float*)p_fc7,
                                       NROI, FCDIM, FCDIM);

    head_kernel<<<NROI, 256>>>(Wloc, bloc, Wsc, bsc);
    post_kernel<<<(NROI + 255) / 256, 256>>>(rois, out);
    nms_kernel<<<10, NROI>>>(out);
}

// round 4
// speedup vs baseline: 2.9377x; 2.9377x over previous
#include <cuda_runtime.h>
#include <cuda_bf16.h>
#include <math.h>
#include <stdint.h>

#define NROI 512
#define NCH 512
#define HF 37
#define WF 50
#define NCLS 11
#define POOLDIM 25088   // NCH * 7 * 7
#define FCDIM 4096

// ---------------- scratch (device globals; no allocation allowed) ----------
__device__ float g_pool[(size_t)NROI * POOLDIM];   // 51.4 MB
__device__ float g_fc1[(size_t)NROI * FCDIM];
__device__ float g_fc7[(size_t)NROI * FCDIM];
__device__ float g_ls[NROI * 55];
__device__ float g_bbox[NROI * 44];
__device__ float g_prob[NROI * 11];

__device__ __forceinline__ float neg_inf() { return __int_as_float(0xff800000); }
__device__ __forceinline__ float pos_inf() { return __int_as_float(0x7f800000); }

// ========================= PTX helpers (baseline ISA only) =================
__device__ __forceinline__ uint32_t smem_u32(const void* p) {
    uint32_t a;
    asm("{ .reg .u64 t; cvta.to.shared.u64 t, %1; cvt.u32.u64 %0, t; }" : "=r"(a) : "l"(p));
    return a;
}
// pack two fp32 -> bf16x2 (first arg -> low 16 bits)
__device__ __forceinline__ uint32_t pack_bf16x2(float lo, float hi) {
    uint32_t r;
    asm("cvt.rn.bf16x2.f32 %0, %1, %2;" : "=r"(r) : "f"(hi), "f"(lo));
    return r;
}

#define LDM_X4(r, a) \
    asm volatile("ldmatrix.sync.aligned.m8n8.x4.shared.b16 {%0,%1,%2,%3}, [%4];" \
        : "=r"((r)[0]), "=r"((r)[1]), "=r"((r)[2]), "=r"((r)[3]) : "r"(a))
#define LDM_X4T(r, a) \
    asm volatile("ldmatrix.sync.aligned.m8n8.x4.trans.shared.b16 {%0,%1,%2,%3}, [%4];" \
        : "=r"((r)[0]), "=r"((r)[1]), "=r"((r)[2]), "=r"((r)[3]) : "r"(a))

__device__ __forceinline__ void mma16816(float* c, const uint32_t* a, uint32_t b0, uint32_t b1) {
    asm volatile(
        "mma.sync.aligned.m16n8k16.row.col.f32.bf16.bf16.f32 "
        "{%0,%1,%2,%3}, {%4,%5,%6,%7}, {%8,%9}, {%0,%1,%2,%3};"
        : "+f"(c[0]), "+f"(c[1]), "+f"(c[2]), "+f"(c[3])
        : "r"(a[0]), "r"(a[1]), "r"(a[2]), "r"(a[3]), "r"(b0), "r"(b1));
}

// ========================= split-bf16 HMMA GEMM ============================
// C[M,N] = relu?(A*B + bias); A MxK, B KxN, C MxN, all fp32 row-major.
// fp32 = hi + lo (bf16); acc += Ahi*Bhi + Ahi*Blo + Alo*Bhi  (ll term ~1e-5, dropped)
// Tile: 128x128x32, 256 threads (8 warps of 64x32), double buffered.
// SMEM per stage: AHi[128][32] ALo BHi[32][128] BLo, 8KB each = 32KB; x2 = 64KB.
#define ST_AHI 0
#define ST_ALO 8192
#define ST_BHI 16384
#define ST_BLO 24576
#define STAGE_SZ 32768
#define GEMM_SMEM 65536

// A tile swizzled offset: row m (0..127) of 64B; 16B chunk index (k>>3) xor'd.
__device__ __forceinline__ uint32_t aoff(int m, int k) {
    return (uint32_t)(m * 64 + ((((k >> 3) ^ ((m >> 1) ^ (m >> 3))) & 3) << 4) + (k & 7) * 2);
}
// B tile [k][n]: row k (0..31) of 256B; chunk (n>>3) xor (k&7).
__device__ __forceinline__ uint32_t boff(int k, int n) {
    return (uint32_t)(k * 256 + ((((n >> 3) ^ (k & 7)) & 15) << 4) + (n & 7) * 2);
}

template <bool RELU>
__global__ void __launch_bounds__(256, 1)
mma_fc_kernel(const float* __restrict__ A, const float* __restrict__ B,
              const float* __restrict__ bias, float* __restrict__ C,
              int N, int K) {
    extern __shared__ char smem[];
    uint32_t sbase = smem_u32(smem);
    const int t = threadIdx.x;
    const int lane = t & 31;
    const int wid = t >> 5;
    const int wy = wid & 1;          // 2 warps over M (64 each)
    const int wx = wid >> 1;         // 4 warps over N (32 each)
    const int m0 = blockIdx.y * 128;
    const int n0 = blockIdx.x * 128;

    // global staging indices
    const int am = t >> 1;                 // A row within tile
    const int ak = (t & 1) * 16;           // A k start
    const int bk = t >> 3;                 // B k row within tile
    const int bn = (t & 7) * 16;           // B n start

    float4 av[4], bv[4];
    const int nit = K / 32;

    float acc[4][4][4];
    #pragma unroll
    for (int i = 0; i < 4; i++)
        #pragma unroll
        for (int j = 0; j < 4; j++)
            #pragma unroll
            for (int e = 0; e < 4; e++) acc[i][j][e] = 0.0f;

    // ---- helpers as macros over locals ----
#define LOAD_GLOBAL(kg) do {                                                   \
        const float* ap_ = A + (size_t)(m0 + am) * K + (kg) + ak;              \
        av[0] = *(const float4*)(ap_ + 0);  av[1] = *(const float4*)(ap_ + 4); \
        av[2] = *(const float4*)(ap_ + 8);  av[3] = *(const float4*)(ap_ + 12);\
        const float* bp_ = B + (size_t)((kg) + bk) * N + n0 + bn;              \
        bv[0] = *(const float4*)(bp_ + 0);  bv[1] = *(const float4*)(bp_ + 4); \
        bv[2] = *(const float4*)(bp_ + 8);  bv[3] = *(const float4*)(bp_ + 12);\
    } while (0)

#define CVT8(src0, src1, h, l) do {                                            \
        (h)[0] = pack_bf16x2((src0).x, (src0).y);                              \
        (h)[1] = pack_bf16x2((src0).z, (src0).w);                              \
        (h)[2] = pack_bf16x2((src1).x, (src1).y);                              \
        (h)[3] = pack_bf16x2((src1).z, (src1).w);                              \
        (l)[0] = pack_bf16x2((src0).x - __uint_as_float((h)[0] << 16),         \
                             (src0).y - __uint_as_float((h)[0] & 0xffff0000u));\
        (l)[1] = pack_bf16x2((src0).z - __uint_as_float((h)[1] << 16),         \
                             (src0).w - __uint_as_float((h)[1] & 0xffff0000u));\
        (l)[2] = pack_bf16x2((src1).x - __uint_as_float((h)[2] << 16),         \
                             (src1).y - __uint_as_float((h)[2] & 0xffff0000u));\
        (l)[3] = pack_bf16x2((src1).z - __uint_as_float((h)[3] << 16),         \
                             (src1).w - __uint_as_float((h)[3] & 0xffff0000u));\
    } while (0)

#define STS_TILES(stg) do {                                                    \
        char* s_ = smem + (stg) * STAGE_SZ;                                    \
        uint32_t h_[4], l_[4];                                                 \
        CVT8(av[0], av[1], h_, l_);                                            \
        *(uint4*)(s_ + ST_AHI + aoff(am, ak))     = make_uint4(h_[0],h_[1],h_[2],h_[3]); \
        *(uint4*)(s_ + ST_ALO + aoff(am, ak))     = make_uint4(l_[0],l_[1],l_[2],l_[3]); \
        CVT8(av[2], av[3], h_, l_);                                            \
        *(uint4*)(s_ + ST_AHI + aoff(am, ak + 8)) = make_uint4(h_[0],h_[1],h_[2],h_[3]); \
        *(uint4*)(s_ + ST_ALO + aoff(am, ak + 8)) = make_uint4(l_[0],l_[1],l_[2],l_[3]); \
        CVT8(bv[0], bv[1], h_, l_);                                            \
        *(uint4*)(s_ + ST_BHI + boff(bk, bn))     = make_uint4(h_[0],h_[1],h_[2],h_[3]); \
        *(uint4*)(s_ + ST_BLO + boff(bk, bn))     = make_uint4(l_[0],l_[1],l_[2],l_[3]); \
        CVT8(bv[2], bv[3], h_, l_);                                            \
        *(uint4*)(s_ + ST_BHI + boff(bk, bn + 8)) = make_uint4(h_[0],h_[1],h_[2],h_[3]); \
        *(uint4*)(s_ + ST_BLO + boff(bk, bn + 8)) = make_uint4(l_[0],l_[1],l_[2],l_[3]); \
    } while (0)

    // prologue
    LOAD_GLOBAL(0);
    STS_TILES(0);
    __syncthreads();

    const int arow_l = lane & 15;
    const int khalf = (lane >> 4) << 3;     // 0 or 8

    for (int it = 0; it < nit; it++) {
        if (it + 1 < nit) LOAD_GLOBAL((it + 1) * 32);

        uint32_t sA_hi = sbase + (uint32_t)((it & 1) * STAGE_SZ) + ST_AHI;
        uint32_t sA_lo = sA_hi + (ST_ALO - ST_AHI);
        uint32_t sB_hi = sbase + (uint32_t)((it & 1) * STAGE_SZ) + ST_BHI;
        uint32_t sB_lo = sB_hi + (ST_BLO - ST_BHI);

        #pragma unroll
        for (int ks = 0; ks < 2; ks++) {
            const int k0 = ks * 16;
            uint32_t ah[4][4], al[4][4], bh[2][4], bl[2][4];
            #pragma unroll
            for (int mi = 0; mi < 4; mi++) {
                int mrow = wy * 64 + mi * 16 + arow_l;
                uint32_t oa = aoff(mrow, k0 + khalf);
                LDM_X4(ah[mi], sA_hi + oa);
                LDM_X4(al[mi], sA_lo + oa);
            }
            #pragma unroll
            for (int nt = 0; nt < 2; nt++) {
                int krow = k0 + (lane & 15);
                int ncol = wx * 32 + nt * 16 + khalf;
                uint32_t ob = boff(krow, ncol);
                LDM_X4T(bh[nt], sB_hi + ob);
                LDM_X4T(bl[nt], sB_lo + ob);
            }
            #pragma unroll
            for (int mi = 0; mi < 4; mi++) {
                #pragma unroll
                for (int ni = 0; ni < 4; ni++) {
                    int nt = ni >> 1;
                    int o = (ni & 1) * 2;
                    mma16816(acc[mi][ni], ah[mi], bh[nt][o], bh[nt][o + 1]);
                    mma16816(acc[mi][ni], ah[mi], bl[nt][o], bl[nt][o + 1]);
                    mma16816(acc[mi][ni], al[mi], bh[nt][o], bh[nt][o + 1]);
                }
            }
        }
        if (it + 1 < nit) STS_TILES((it + 1) & 1);
        __syncthreads();
    }

    // ---- epilogue: bias + relu + store ----
    #pragma unroll
    for (int mi = 0; mi < 4; mi++) {
        int mrow = m0 + wy * 64 + mi * 16 + (lane >> 2);
        #pragma unroll
        for (int ni = 0; ni < 4; ni++) {
            int ncol = n0 + wx * 32 + ni * 8 + (lane & 3) * 2;
            float bb0 = bias[ncol], bb1 = bias[ncol + 1];
            float v0 = acc[mi][ni][0] + bb0;
            float v1 = acc[mi][ni][1] + bb1;
            float v2 = acc[mi][ni][2] + bb0;
            float v3 = acc[mi][ni][3] + bb1;
            if (RELU) {
                v0 = fmaxf(v0, 0.0f); v1 = fmaxf(v1, 0.0f);
                v2 = fmaxf(v2, 0.0f); v3 = fmaxf(v3, 0.0f);
            }
            *(float2*)(C + (size_t)mrow * N + ncol)       = make_float2(v0, v1);
            *(float2*)(C + (size_t)(mrow + 8) * N + ncol) = make_float2(v2, v3);
        }
    }
#undef LOAD_GLOBAL
#undef CVT8
#undef STS_TILES
}

// ---------------- 1. ROI max-pool ------------------------------------------
__global__ void roipool_kernel(const float* __restrict__ feat,
                               const float* __restrict__ rois,
                               const int* __restrict__ roi_idx) {
    int r = blockIdx.x;
    __shared__ int hs[7], he[7], ws[7], we[7];
    if (threadIdx.x == 0) {
        const float RECIP7 = 1.0f / 7.0f;   // matches XLA's x/7 -> x*recip rewrite
        float y1 = rois[r * 4 + 0], x1 = rois[r * 4 + 1];
        float y2 = rois[r * 4 + 2], x2 = rois[r * 4 + 3];
        float sw = rintf(x1 * 0.0625f);
        float ew = rintf(x2 * 0.0625f);
        float sh = rintf(y1 * 0.0625f);
        float eh = rintf(y2 * 0.0625f);
        float rw = fmaxf(ew - sw + 1.0f, 1.0f);
        float rh = fmaxf(eh - sh + 1.0f, 1.0f);
        #pragma unroll
        for (int p = 0; p < 7; p++) {
            float fp = (float)p;
            float h0 = floorf(__fmul_rn(fp * rh, RECIP7)) + sh;
            float h1 = ceilf(__fmul_rn((fp + 1.0f) * rh, RECIP7)) + sh;
            float w0 = floorf(__fmul_rn(fp * rw, RECIP7)) + sw;
            float w1 = ceilf(__fmul_rn((fp + 1.0f) * rw, RECIP7)) + sw;
            hs[p] = (int)fminf(fmaxf(h0, 0.0f), (float)HF);
            he[p] = (int)fminf(fmaxf(h1, 0.0f), (float)HF);
            ws[p] = (int)fminf(fmaxf(w0, 0.0f), (float)WF);
            we[p] = (int)fminf(fmaxf(w1, 0.0f), (float)WF);
        }
    }
    __syncthreads();
    int b = roi_idx[r];
    const float* f = feat + (size_t)b * NCH * HF * WF;
    for (int idx = threadIdx.x; idx < POOLDIM; idx += blockDim.x) {
        int c = idx / 49;
        int rem = idx - c * 49;
        int ph = rem / 7, pw = rem - (rem / 7) * 7;
        int h0 = hs[ph], h1 = he[ph], w0 = ws[pw], w1 = we[pw];
        float m = 0.0f;
        if (h1 > h0 && w1 > w0) {
            m = neg_inf();
            const float* fc_ = f + (size_t)c * (HF * WF);
            for (int y = h0; y < h1; y++)
                for (int x = w0; x < w1; x++)
                    m = fmaxf(m, fc_[y * WF + x]);
        }
        g_pool[(size_t)r * POOLDIM + idx] = m;
    }
}

// ---------------- 3. loc + score heads, tiled ------------------------------
__global__ void __launch_bounds__(256) head_kernel(const float* __restrict__ Wloc,
                                                   const float* __restrict__ bloc,
                                                   const float* __restrict__ Wsc,
                                                   const float* __restrict__ bsc) {
    __shared__ float Ws[128][57];
    __shared__ float Fs[8][128];
    int t = threadIdx.x;
    int r0 = blockIdx.x * 8;
    int o0 = t, o1 = t + 256;
    int roi0 = o0 / 55, col0 = o0 - roi0 * 55;
    int roi1 = o1 / 55, col1 = o1 - roi1 * 55;
    float acc0 = 0.0f, acc1 = 0.0f;
    for (int kc = 0; kc < FCDIM; kc += 128) {
        __syncthreads();
        for (int i = t; i < 128 * 44; i += 256) {
            int kk = i / 44, c = i - kk * 44;
            Ws[kk][c] = Wloc[(size_t)(kc + kk) * 44 + c];
        }
        for (int i = t; i < 128 * 11; i += 256) {
            int kk = i / 11, c = i - kk * 11;
            Ws[kk][44 + c] = Wsc[(size_t)(kc + kk) * 11 + c];
        }
        for (int i = t; i < 8 * 128; i += 256) {
            int ri = i >> 7, k = i & 127;
            Fs[ri][k] = g_fc7[(size_t)(r0 + ri) * FCDIM + kc + k];
        }
        __syncthreads();
        #pragma unroll 4
        for (int k = 0; k < 128; k++) {
            acc0 = fmaf(Fs[roi0][k], Ws[k][col0], acc0);
            if (o1 < 440) acc1 = fmaf(Fs[roi1][k], Ws[k][col1], acc1);
        }
    }
    float bb0 = (col0 < 44) ? bloc[col0] : bsc[col0 - 44];
    g_ls[(r0 + roi0) * 55 + col0] = acc0 + bb0;
    if (o1 < 440) {
        float bb1 = (col1 < 44) ? bloc[col1] : bsc[col1 - 44];
        g_ls[(r0 + roi1) * 55 + col1] = acc1 + bb1;
    }
}

// ---------------- 4. bbox decode + clip + softmax ---------------------------
__global__ void post_kernel(const float* __restrict__ rois, float* __restrict__ out) {
    int r = blockIdx.x * blockDim.x + threadIdx.x;
    if (r >= NROI) return;
    float y1 = rois[r * 4 + 0], x1 = rois[r * 4 + 1];
    float y2 = rois[r * 4 + 2], x2 = rois[r * 4 + 3];
    float sh_ = y2 - y1, sw_ = x2 - x1;
    float cy = y1 + 0.5f * sh_, cx = x1 + 0.5f * sw_;
    #pragma unroll
    for (int c = 0; c < NCLS; c++) {
        float dy = g_ls[r * 55 + c * 4 + 0] * 0.1f;
        float dx = g_ls[r * 55 + c * 4 + 1] * 0.1f;
        float dh = g_ls[r * 55 + c * 4 + 2] * 0.2f;
        float dw = g_ls[r * 55 + c * 4 + 3] * 0.2f;
        float ncy = dy * sh_ + cy;
        float ncx = dx * sw_ + cx;
        float nh = expf(dh) * sh_;
        float nw = expf(dw) * sw_;
        float by1 = fminf(fmaxf(ncy - 0.5f * nh, 0.0f), 600.0f);
        float bx1 = fminf(fmaxf(ncx - 0.5f * nw, 0.0f), 800.0f);
        float by2 = fminf(fmaxf(ncy + 0.5f * nh, 0.0f), 600.0f);
        float bx2 = fminf(fmaxf(ncx + 0.5f * nw, 0.0f), 800.0f);
        g_bbox[r * 44 + c * 4 + 0] = by1;
        g_bbox[r * 44 + c * 4 + 1] = bx1;
        g_bbox[r * 44 + c * 4 + 2] = by2;
        g_bbox[r * 44 + c * 4 + 3] = bx2;
        out[r * 44 + c * 4 + 0] = by1;
        out[r * 44 + c * 4 + 1] = bx1;
        out[r * 44 + c * 4 + 2] = by2;
        out[r * 44 + c * 4 + 3] = bx2;
    }
    float sc[NCLS];
    float mx = neg_inf();
    #pragma unroll
    for (int c = 0; c < NCLS; c++) {
        sc[c] = g_ls[r * 55 + 44 + c];
        mx = fmaxf(mx, sc[c]);
    }
    float sum = 0.0f;
    #pragma unroll
    for (int c = 0; c < NCLS; c++) { sc[c] = expf(sc[c] - mx); sum += sc[c]; }
    #pragma unroll
    for (int c = 0; c < NCLS; c++) {
        float p = sc[c] / sum;
        g_prob[r * 11 + c] = p;
        out[NROI * 44 + r * 11 + c] = p;
    }
}

// ---------------- 5. per-class NMS ------------------------------------------
__global__ void __launch_bounds__(512) nms_kernel(float* __restrict__ out) {
    int cls = blockIdx.x + 1;
    int j = threadIdx.x;
    __shared__ float key[NROI];
    __shared__ int order[NROI];
    __shared__ float4 sb[NROI];
    __shared__ unsigned char keep[NROI];

    float s = g_prob[j * 11 + cls];
    bool valid = s > 0.05f;
    float kj = valid ? -s : pos_inf();
    key[j] = kj;
    __syncthreads();
    int rank = 0;
    for (int i = 0; i < NROI; i++) {
        float ki = key[i];
        rank += (ki < kj) || (ki == kj && i < j);
    }
    order[rank] = j;
    __syncthreads();
    int src = order[j];
    float4 box = *(const float4*)&g_bbox[src * 44 + cls * 4];
    sb[j] = box;
    keep[j] = (g_prob[src * 11 + cls] > 0.05f) ? 1 : 0;
    __syncthreads();

    float areaJ = (box.z - box.x) * (box.w - box.y);
    for (int i = 0; i < NROI - 1; i++) {
        if (keep[i] && j > i && keep[j]) {
            float4 bi = sb[i];
            float ty_ = fmaxf(box.x, bi.x);
            float tx_ = fmaxf(box.y, bi.y);
            float by_ = fminf(box.z, bi.z);
            float bx_ = fminf(box.w, bi.w);
            float ih = fmaxf(by_ - ty_, 0.0f);
            float iw = fmaxf(bx_ - tx_, 0.0f);
            float inter = ih * iw;
            float areaI = (bi.z - bi.x) * (bi.w - bi.y);
            float iou = inter / (areaJ + areaI - inter);
            if (iou > 0.3f) keep[j] = 0;
        }
        __syncthreads();
    }
    out[NROI * 44 + NROI * 11 + blockIdx.x * NROI + src] = keep[j] ? 1.0f : 0.0f;
}

// ---------------- launch ----------------------------------------------------
extern "C" void kernel_launch(void* const* d_in, const int* in_sizes, int n_in,
                              void* d_out, int out_size) {
    (void)in_sizes; (void)n_in; (void)out_size;
    const float* h    = (const float*)d_in[0];
    const float* rois = (const float*)d_in[1];
    const int*   ridx = (const int*)d_in[2];
    const float* W1   = (const float*)d_in[3];
    const float* b1   = (const float*)d_in[4];
    const float* W2   = (const float*)d_in[5];
    const float* b2   = (const float*)d_in[6];
    const float* Wloc = (const float*)d_in[7];
    const float* bloc = (const float*)d_in[8];
    const float* Wsc  = (const float*)d_in[9];
    const float* bsc  = (const float*)d_in[10];
    float* out = (float*)d_out;

    void *p_pool, *p_fc1, *p_fc7;
    cudaGetSymbolAddress(&p_pool, g_pool);
    cudaGetSymbolAddress(&p_fc1, g_fc1);
    cudaGetSymbolAddress(&p_fc7, g_fc7);

    cudaFuncSetAttribute(mma_fc_kernel<true>,
                         cudaFuncAttributeMaxDynamicSharedMemorySize, GEMM_SMEM);

    roipool_kernel<<<NROI, 256>>>(h, rois, ridx);

    dim3 grid(FCDIM / 128, NROI / 128);   // (32, 4)
    mma_fc_kernel<true><<<grid, 256, GEMM_SMEM>>>(
        (const float*)p_pool, W1, b1, (float*)p_fc1, FCDIM, POOLDIM);
    mma_fc_kernel<true><<<grid, 256, GEMM_SMEM>>>(
        (const float*)p_fc1, W2, b2, (float*)p_fc7, FCDIM, FCDIM);

    head_kernel<<<64, 256>>>(Wloc, bloc, Wsc, bsc);
    post_kernel<<<(NROI + 255) / 256, 256>>>(rois, out);
    nms_kernel<<<10, NROI>>>(out);
}

// round 5
// speedup vs baseline: 3.1677x; 1.0783x over previous
#include <cuda_runtime.h>
#include <cuda_bf16.h>
#include <math.h>
#include <stdint.h>

#define NROI 512
#define NCH 512
#define HF 37
#define WF 50
#define NCLS 11
#define POOLDIM 25088   // NCH * 7 * 7
#define FCDIM 4096

// ---------------- scratch (device globals; no allocation allowed) ----------
__device__ __nv_bfloat16 g_poolh[(size_t)NROI * POOLDIM];
__device__ __nv_bfloat16 g_pooll[(size_t)NROI * POOLDIM];
__device__ __nv_bfloat16 g_W1h[(size_t)POOLDIM * FCDIM];
__device__ __nv_bfloat16 g_W1l[(size_t)POOLDIM * FCDIM];
__device__ __nv_bfloat16 g_W2h[(size_t)FCDIM * FCDIM];
__device__ __nv_bfloat16 g_W2l[(size_t)FCDIM * FCDIM];
__device__ __nv_bfloat16 g_fc1h[(size_t)NROI * FCDIM];
__device__ __nv_bfloat16 g_fc1l[(size_t)NROI * FCDIM];
__device__ float g_fc7[(size_t)NROI * FCDIM];
__device__ float g_Wt[55 * FCDIM];
__device__ float g_ls[NROI * 55];
__device__ float g_bbox[NROI * 44];
__device__ float g_prob[NROI * 11];

__device__ __forceinline__ float neg_inf() { return __int_as_float(0xff800000); }
__device__ __forceinline__ float pos_inf() { return __int_as_float(0x7f800000); }

// ========================= PTX helpers (baseline ISA only) =================
__device__ __forceinline__ uint32_t smem_u32(const void* p) {
    uint32_t a;
    asm("{ .reg .u64 t; cvta.to.shared.u64 t, %1; cvt.u32.u64 %0, t; }" : "=r"(a) : "l"(p));
    return a;
}
// pack two fp32 -> bf16x2 (first arg -> low 16 bits)
__device__ __forceinline__ uint32_t pack_bf16x2(float lo, float hi) {
    uint32_t r;
    asm("cvt.rn.bf16x2.f32 %0, %1, %2;" : "=r"(r) : "f"(hi), "f"(lo));
    return r;
}

#define LDM_X4(r, a) \
    asm volatile("ldmatrix.sync.aligned.m8n8.x4.shared.b16 {%0,%1,%2,%3}, [%4];" \
        : "=r"((r)[0]), "=r"((r)[1]), "=r"((r)[2]), "=r"((r)[3]) : "r"(a))
#define LDM_X4T(r, a) \
    asm volatile("ldmatrix.sync.aligned.m8n8.x4.trans.shared.b16 {%0,%1,%2,%3}, [%4];" \
        : "=r"((r)[0]), "=r"((r)[1]), "=r"((r)[2]), "=r"((r)[3]) : "r"(a))

__device__ __forceinline__ void mma16816(float* c, const uint32_t* a, uint32_t b0, uint32_t b1) {
    asm volatile(
        "mma.sync.aligned.m16n8k16.row.col.f32.bf16.bf16.f32 "
        "{%0,%1,%2,%3}, {%4,%5,%6,%7}, {%8,%9}, {%0,%1,%2,%3};"
        : "+f"(c[0]), "+f"(c[1]), "+f"(c[2]), "+f"(c[3])
        : "r"(a[0]), "r"(a[1]), "r"(a[2]), "r"(a[3]), "r"(b0), "r"(b1));
}

#define CP16(dst, src) \
    asm volatile("cp.async.cg.shared.global [%0], [%1], 16;" :: "r"(dst), "l"(src))
#define CP_COMMIT() asm volatile("cp.async.commit_group;" ::: "memory")
#define CP_WAIT0() asm volatile("cp.async.wait_group 0;" ::: "memory")
#define CP_WAIT1() asm volatile("cp.async.wait_group 1;" ::: "memory")

// ========================= split-bf16 HMMA GEMM ============================
// C = relu(A*B + bias); A MxK, B KxN (both pre-split bf16 hi/lo), C fp32 or split.
// acc += Ahi*Bhi + Ahi*Blo + Alo*Bhi  (3 passes, fp32 accum)
// Tile 128x128x32, 256 threads (8 warps of 64x32), 2-stage cp.async pipeline.
#define ST_AHI 0
#define ST_ALO 8192
#define ST_BHI 16384
#define ST_BLO 24576
#define STAGE_SZ 32768
#define GEMM_SMEM 65536

__device__ __forceinline__ uint32_t aoff(int m, int k) {
    return (uint32_t)(m * 64 + ((((k >> 3) ^ ((m >> 1) ^ (m >> 3))) & 3) << 4) + (k & 7) * 2);
}
__device__ __forceinline__ uint32_t boff(int k, int n) {
    return (uint32_t)(k * 256 + ((((n >> 3) ^ (k & 7)) & 15) << 4) + (n & 7) * 2);
}

// OUT: 0 = fp32 out (Cf), 1 = split bf16 out (Ch, Cl)
template <int OUT>
__global__ void __launch_bounds__(256, 1)
mma_fc_kernel(const __nv_bfloat16* __restrict__ Ah, const __nv_bfloat16* __restrict__ Al,
              const __nv_bfloat16* __restrict__ Bh, const __nv_bfloat16* __restrict__ Bl,
              const float* __restrict__ bias, float* __restrict__ Cf,
              __nv_bfloat16* __restrict__ Ch, __nv_bfloat16* __restrict__ Cl,
              int N, int K) {
    extern __shared__ char smem[];
    uint32_t sbase = smem_u32(smem);
    const int t = threadIdx.x;
    const int lane = t & 31;
    const int wid = t >> 5;
    const int wy = wid & 1;
    const int wx = wid >> 1;
    const int m0 = blockIdx.y * 128;
    const int n0 = blockIdx.x * 128;

    const int am = t >> 1;
    const int ak = (t & 1) * 16;
    const int bk = t >> 3;
    const int bn = (t & 7) * 16;

    const int nit = K / 32;

    float acc[4][4][4];
    #pragma unroll
    for (int i = 0; i < 4; i++)
        #pragma unroll
        for (int j = 0; j < 4; j++)
            #pragma unroll
            for (int e = 0; e < 4; e++) acc[i][j][e] = 0.0f;

#define ISSUE(stg, kg) do {                                                    \
        uint32_t s_ = sbase + (uint32_t)(stg) * STAGE_SZ;                      \
        const __nv_bfloat16* ah_ = Ah + (size_t)(m0 + am) * K + (kg) + ak;     \
        const __nv_bfloat16* al_ = Al + (size_t)(m0 + am) * K + (kg) + ak;     \
        CP16(s_ + ST_AHI + aoff(am, ak),     ah_);                             \
        CP16(s_ + ST_AHI + aoff(am, ak + 8), ah_ + 8);                         \
        CP16(s_ + ST_ALO + aoff(am, ak),     al_);                             \
        CP16(s_ + ST_ALO + aoff(am, ak + 8), al_ + 8);                         \
        const __nv_bfloat16* bh_ = Bh + (size_t)((kg) + bk) * N + n0 + bn;     \
        const __nv_bfloat16* bl_ = Bl + (size_t)((kg) + bk) * N + n0 + bn;     \
        CP16(s_ + ST_BHI + boff(bk, bn),     bh_);                             \
        CP16(s_ + ST_BHI + boff(bk, bn + 8), bh_ + 8);                         \
        CP16(s_ + ST_BLO + boff(bk, bn),     bl_);                             \
        CP16(s_ + ST_BLO + boff(bk, bn + 8), bl_ + 8);                         \
        CP_COMMIT();                                                           \
    } while (0)

    ISSUE(0, 0);
    ISSUE(1, 32);

    const int arow_l = lane & 15;
    const int khalf = (lane >> 4) << 3;

    for (int it = 0; it < nit; it++) {
        if (it == nit - 1) { CP_WAIT0(); } else { CP_WAIT1(); }
        __syncthreads();

        uint32_t sA_hi = sbase + (uint32_t)((it & 1) * STAGE_SZ) + ST_AHI;
        uint32_t sA_lo = sA_hi + (ST_ALO - ST_AHI);
        uint32_t sB_hi = sbase + (uint32_t)((it & 1) * STAGE_SZ) + ST_BHI;
        uint32_t sB_lo = sB_hi + (ST_BLO - ST_BHI);

        #pragma unroll
        for (int ks = 0; ks < 2; ks++) {
            const int k0 = ks * 16;
            uint32_t ah[4][4], al[4][4], bh[2][4], bl[2][4];
            #pragma unroll
            for (int mi = 0; mi < 4; mi++) {
                int mrow = wy * 64 + mi * 16 + arow_l;
                uint32_t oa = aoff(mrow, k0 + khalf);
                LDM_X4(ah[mi], sA_hi + oa);
                LDM_X4(al[mi], sA_lo + oa);
            }
            #pragma unroll
            for (int nt = 0; nt < 2; nt++) {
                int krow = k0 + (lane & 15);
                int ncol = wx * 32 + nt * 16 + khalf;
                uint32_t ob = boff(krow, ncol);
                LDM_X4T(bh[nt], sB_hi + ob);
                LDM_X4T(bl[nt], sB_lo + ob);
            }
            #pragma unroll
            for (int mi = 0; mi < 4; mi++) {
                #pragma unroll
                for (int ni = 0; ni < 4; ni++) {
                    int nt = ni >> 1;
                    int o = (ni & 1) * 2;
                    mma16816(acc[mi][ni], ah[mi], bh[nt][o], bh[nt][o + 1]);
                    mma16816(acc[mi][ni], ah[mi], bl[nt][o], bl[nt][o + 1]);
                    mma16816(acc[mi][ni], al[mi], bh[nt][o], bh[nt][o + 1]);
                }
            }
        }
        __syncthreads();
        if (it + 2 < nit) ISSUE(it & 1, (it + 2) * 32);
    }

    // ---- epilogue: bias + relu + store ----
    #pragma unroll
    for (int mi = 0; mi < 4; mi++) {
        int mrow = m0 + wy * 64 + mi * 16 + (lane >> 2);
        #pragma unroll
        for (int ni = 0; ni < 4; ni++) {
            int ncol = n0 + wx * 32 + ni * 8 + (lane & 3) * 2;
            float bb0 = bias[ncol], bb1 = bias[ncol + 1];
            float v0 = fmaxf(acc[mi][ni][0] + bb0, 0.0f);
            float v1 = fmaxf(acc[mi][ni][1] + bb1, 0.0f);
            float v2 = fmaxf(acc[mi][ni][2] + bb0, 0.0f);
            float v3 = fmaxf(acc[mi][ni][3] + bb1, 0.0f);
            if (OUT == 0) {
                *(float2*)(Cf + (size_t)mrow * N + ncol)       = make_float2(v0, v1);
                *(float2*)(Cf + (size_t)(mrow + 8) * N + ncol) = make_float2(v2, v3);
            } else {
                uint32_t h01 = pack_bf16x2(v0, v1);
                uint32_t l01 = pack_bf16x2(v0 - __uint_as_float(h01 << 16),
                                           v1 - __uint_as_float(h01 & 0xffff0000u));
                uint32_t h23 = pack_bf16x2(v2, v3);
                uint32_t l23 = pack_bf16x2(v2 - __uint_as_float(h23 << 16),
                                           v3 - __uint_as_float(h23 & 0xffff0000u));
                *(uint32_t*)(Ch + (size_t)mrow * N + ncol)       = h01;
                *(uint32_t*)(Cl + (size_t)mrow * N + ncol)       = l01;
                *(uint32_t*)(Ch + (size_t)(mrow + 8) * N + ncol) = h23;
                *(uint32_t*)(Cl + (size_t)(mrow + 8) * N + ncol) = l23;
            }
        }
    }
#undef ISSUE
}

// ---------------- 0. fp32 -> bf16 hi/lo split (streaming) -------------------
__global__ void split_kernel(const float* __restrict__ src,
                             __nv_bfloat16* __restrict__ hi,
                             __nv_bfloat16* __restrict__ lo, size_t n4) {
    size_t stride = (size_t)gridDim.x * blockDim.x;
    for (size_t i = (size_t)blockIdx.x * blockDim.x + threadIdx.x; i < n4; i += stride) {
        float4 v = ((const float4*)src)[i];
        uint32_t h0 = pack_bf16x2(v.x, v.y);
        uint32_t h1 = pack_bf16x2(v.z, v.w);
        uint32_t l0 = pack_bf16x2(v.x - __uint_as_float(h0 << 16),
                                  v.y - __uint_as_float(h0 & 0xffff0000u));
        uint32_t l1 = pack_bf16x2(v.z - __uint_as_float(h1 << 16),
                                  v.w - __uint_as_float(h1 & 0xffff0000u));
        ((uint2*)hi)[i] = make_uint2(h0, h1);
        ((uint2*)lo)[i] = make_uint2(l0, l1);
    }
}

// ---------------- 1. ROI max-pool (emits bf16 hi/lo directly) ---------------
__global__ void roipool_kernel(const float* __restrict__ feat,
                               const float* __restrict__ rois,
                               const int* __restrict__ roi_idx) {
    int r = blockIdx.x;
    __shared__ int hs[7], he[7], ws[7], we[7];
    if (threadIdx.x == 0) {
        const float RECIP7 = 1.0f / 7.0f;   // matches XLA's x/7 -> x*recip rewrite
        float y1 = rois[r * 4 + 0], x1 = rois[r * 4 + 1];
        float y2 = rois[r * 4 + 2], x2 = rois[r * 4 + 3];
        float sw = rintf(x1 * 0.0625f);
        float ew = rintf(x2 * 0.0625f);
        float sh = rintf(y1 * 0.0625f);
        float eh = rintf(y2 * 0.0625f);
        float rw = fmaxf(ew - sw + 1.0f, 1.0f);
        float rh = fmaxf(eh - sh + 1.0f, 1.0f);
        #pragma unroll
        for (int p = 0; p < 7; p++) {
            float fp = (float)p;
            float h0 = floorf(__fmul_rn(fp * rh, RECIP7)) + sh;
            float h1 = ceilf(__fmul_rn((fp + 1.0f) * rh, RECIP7)) + sh;
            float w0 = floorf(__fmul_rn(fp * rw, RECIP7)) + sw;
            float w1 = ceilf(__fmul_rn((fp + 1.0f) * rw, RECIP7)) + sw;
            hs[p] = (int)fminf(fmaxf(h0, 0.0f), (float)HF);
            he[p] = (int)fminf(fmaxf(h1, 0.0f), (float)HF);
            ws[p] = (int)fminf(fmaxf(w0, 0.0f), (float)WF);
            we[p] = (int)fminf(fmaxf(w1, 0.0f), (float)WF);
        }
    }
    __syncthreads();
    int b = roi_idx[r];
    const float* f = feat + (size_t)b * NCH * HF * WF;
    for (int idx = threadIdx.x; idx < POOLDIM; idx += blockDim.x) {
        int c = idx / 49;
        int rem = idx - c * 49;
        int ph = rem / 7, pw = rem - (rem / 7) * 7;
        int h0 = hs[ph], h1 = he[ph], w0 = ws[pw], w1 = we[pw];
        float m = 0.0f;
        if (h1 > h0 && w1 > w0) {
            m = neg_inf();
            const float* fc_ = f + (size_t)c * (HF * WF);
            for (int y = h0; y < h1; y++)
                for (int x = w0; x < w1; x++)
                    m = fmaxf(m, fc_[y * WF + x]);
        }
        __nv_bfloat16 hb = __float2bfloat16(m);
        g_poolh[(size_t)r * POOLDIM + idx] = hb;
        g_pooll[(size_t)r * POOLDIM + idx] = __float2bfloat16(m - __bfloat162float(hb));
    }
}

// ---------------- 2. head W transpose: g_Wt[55][4096] ----------------------
__global__ void prep_head_kernel(const float* __restrict__ Wloc,
                                 const float* __restrict__ Wsc) {
    int stride = gridDim.x * blockDim.x;
    for (int i = blockIdx.x * blockDim.x + threadIdx.x; i < 55 * FCDIM; i += stride) {
        int col = i >> 12;
        int k = i & (FCDIM - 1);
        g_Wt[i] = (col < 44) ? Wloc[(size_t)k * 44 + col] : Wsc[(size_t)k * 11 + (col - 44)];
    }
}

// ---------------- 3. heads: 2 ROIs per block, warp-per-output --------------
__global__ void __launch_bounds__(256) head_kernel(const float* __restrict__ bloc,
                                                   const float* __restrict__ bsc) {
    __shared__ float4 Fs[2][FCDIM / 4];
    int r0 = blockIdx.x * 2;
    int t = threadIdx.x;
    for (int i = t; i < 2 * (FCDIM / 4); i += 256) {
        int ri = i >> 10, kk = i & 1023;
        Fs[ri][kk] = ((const float4*)g_fc7)[(size_t)(r0 + ri) * (FCDIM / 4) + kk];
    }
    __syncthreads();
    int w = t >> 5, lane = t & 31;
    for (int o = w; o < 110; o += 8) {
        int roi = (o >= 55) ? 1 : 0;
        int col = o - roi * 55;
        const float4* wp = (const float4*)(g_Wt + col * FCDIM);
        float acc = 0.0f;
        for (int kb = lane; kb < FCDIM / 4; kb += 32) {
            float4 f = Fs[roi][kb];
            float4 v = wp[kb];
            acc = fmaf(f.x, v.x, acc);
            acc = fmaf(f.y, v.y, acc);
            acc = fmaf(f.z, v.z, acc);
            acc = fmaf(f.w, v.w, acc);
        }
        #pragma unroll
        for (int of = 16; of > 0; of >>= 1) acc += __shfl_xor_sync(0xffffffffu, acc, of);
        if (lane == 0) {
            float bb = (col < 44) ? bloc[col] : bsc[col - 44];
            g_ls[(r0 + roi) * 55 + col] = acc + bb;
        }
    }
}

// ---------------- 4. bbox decode + clip + softmax ---------------------------
__global__ void post_kernel(const float* __restrict__ rois, float* __restrict__ out) {
    int r = blockIdx.x * blockDim.x + threadIdx.x;
    if (r >= NROI) return;
    float y1 = rois[r * 4 + 0], x1 = rois[r * 4 + 1];
    float y2 = rois[r * 4 + 2], x2 = rois[r * 4 + 3];
    float sh_ = y2 - y1, sw_ = x2 - x1;
    float cy = y1 + 0.5f * sh_, cx = x1 + 0.5f * sw_;
    #pragma unroll
    for (int c = 0; c < NCLS; c++) {
        float dy = g_ls[r * 55 + c * 4 + 0] * 0.1f;
        float dx = g_ls[r * 55 + c * 4 + 1] * 0.1f;
        float dh = g_ls[r * 55 + c * 4 + 2] * 0.2f;
        float dw = g_ls[r * 55 + c * 4 + 3] * 0.2f;
        float ncy = dy * sh_ + cy;
        float ncx = dx * sw_ + cx;
        float nh = expf(dh) * sh_;
        float nw = expf(dw) * sw_;
        float by1 = fminf(fmaxf(ncy - 0.5f * nh, 0.0f), 600.0f);
        float bx1 = fminf(fmaxf(ncx - 0.5f * nw, 0.0f), 800.0f);
        float by2 = fminf(fmaxf(ncy + 0.5f * nh, 0.0f), 600.0f);
        float bx2 = fminf(fmaxf(ncx + 0.5f * nw, 0.0f), 800.0f);
        g_bbox[r * 44 + c * 4 + 0] = by1;
        g_bbox[r * 44 + c * 4 + 1] = bx1;
        g_bbox[r * 44 + c * 4 + 2] = by2;
        g_bbox[r * 44 + c * 4 + 3] = bx2;
        out[r * 44 + c * 4 + 0] = by1;
        out[r * 44 + c * 4 + 1] = bx1;
        out[r * 44 + c * 4 + 2] = by2;
        out[r * 44 + c * 4 + 3] = bx2;
    }
    float sc[NCLS];
    float mx = neg_inf();
    #pragma unroll
    for (int c = 0; c < NCLS; c++) {
        sc[c] = g_ls[r * 55 + 44 + c];
        mx = fmaxf(mx, sc[c]);
    }
    float sum = 0.0f;
    #pragma unroll
    for (int c = 0; c < NCLS; c++) { sc[c] = expf(sc[c] - mx); sum += sc[c]; }
    #pragma unroll
    for (int c = 0; c < NCLS; c++) {
        float p = sc[c] / sum;
        g_prob[r * 11 + c] = p;
        out[NROI * 44 + r * 11 + c] = p;
    }
}

// ---------------- 5. per-class NMS ------------------------------------------
__global__ void __launch_bounds__(512) nms_kernel(float* __restrict__ out) {
    int cls = blockIdx.x + 1;
    int j = threadIdx.x;
    __shared__ float key[NROI];
    __shared__ int order[NROI];
    __shared__ float4 sb[NROI];
    __shared__ unsigned char keep[NROI];

    float s = g_prob[j * 11 + cls];
    bool valid = s > 0.05f;
    float kj = valid ? -s : pos_inf();
    key[j] = kj;
    __syncthreads();
    int rank = 0;
    for (int i = 0; i < NROI; i++) {
        float ki = key[i];
        rank += (ki < kj) || (ki == kj && i < j);
    }
    order[rank] = j;
    __syncthreads();
    int src = order[j];
    float4 box = *(const float4*)&g_bbox[src * 44 + cls * 4];
    sb[j] = box;
    keep[j] = (g_prob[src * 11 + cls] > 0.05f) ? 1 : 0;
    __syncthreads();

    float areaJ = (box.z - box.x) * (box.w - box.y);
    for (int i = 0; i < NROI - 1; i++) {
        if (keep[i] && j > i && keep[j]) {
            float4 bi = sb[i];
            float ty_ = fmaxf(box.x, bi.x);
            float tx_ = fmaxf(box.y, bi.y);
            float by_ = fminf(box.z, bi.z);
            float bx_ = fminf(box.w, bi.w);
            float ih = fmaxf(by_ - ty_, 0.0f);
            float iw = fmaxf(bx_ - tx_, 0.0f);
            float inter = ih * iw;
            float areaI = (bi.z - bi.x) * (bi.w - bi.y);
            float iou = inter / (areaJ + areaI - inter);
            if (iou > 0.3f) keep[j] = 0;
        }
        __syncthreads();
    }
    out[NROI * 44 + NROI * 11 + blockIdx.x * NROI + src] = keep[j] ? 1.0f : 0.0f;
}

// ---------------- launch ----------------------------------------------------
extern "C" void kernel_launch(void* const* d_in, const int* in_sizes, int n_in,
                              void* d_out, int out_size) {
    (void)in_sizes; (void)n_in; (void)out_size;
    const float* h    = (const float*)d_in[0];
    const float* rois = (const float*)d_in[1];
    const int*   ridx = (const int*)d_in[2];
    const float* W1   = (const float*)d_in[3];
    const float* b1   = (const float*)d_in[4];
    const float* W2   = (const float*)d_in[5];
    const float* b2   = (const float*)d_in[6];
    const float* Wloc = (const float*)d_in[7];
    const float* bloc = (const float*)d_in[8];
    const float* Wsc  = (const float*)d_in[9];
    const float* bsc  = (const float*)d_in[10];
    float* out = (float*)d_out;

    void *p_ph, *p_pl, *p_w1h, *p_w1l, *p_w2h, *p_w2l, *p_f1h, *p_f1l, *p_f7;
    cudaGetSymbolAddress(&p_ph, g_poolh);
    cudaGetSymbolAddress(&p_pl, g_pooll);
    cudaGetSymbolAddress(&p_w1h, g_W1h);
    cudaGetSymbolAddress(&p_w1l, g_W1l);
    cudaGetSymbolAddress(&p_w2h, g_W2h);
    cudaGetSymbolAddress(&p_w2l, g_W2l);
    cudaGetSymbolAddress(&p_f1h, g_fc1h);
    cudaGetSymbolAddress(&p_f1l, g_fc1l);
    cudaGetSymbolAddress(&p_f7, g_fc7);

    cudaFuncSetAttribute(mma_fc_kernel<0>,
                         cudaFuncAttributeMaxDynamicSharedMemorySize, GEMM_SMEM);
    cudaFuncSetAttribute(mma_fc_kernel<1>,
                         cudaFuncAttributeMaxDynamicSharedMemorySize, GEMM_SMEM);

    // independent prep
    roipool_kernel<<<NROI, 256>>>(h, rois, ridx);
    split_kernel<<<4096, 256>>>(W1, (__nv_bfloat16*)p_w1h, (__nv_bfloat16*)p_w1l,
                                (size_t)POOLDIM * FCDIM / 4);
    split_kernel<<<2048, 256>>>(W2, (__nv_bfloat16*)p_w2h, (__nv_bfloat16*)p_w2l,
                                (size_t)FCDIM * FCDIM / 4);
    prep_head_kernel<<<256, 256>>>(Wloc, Wsc);

    dim3 grid(FCDIM / 128, NROI / 128);   // (32, 4)
    mma_fc_kernel<1><<<grid, 256, GEMM_SMEM>>>(
        (const __nv_bfloat16*)p_ph, (const __nv_bfloat16*)p_pl,
        (const __nv_bfloat16*)p_w1h, (const __nv_bfloat16*)p_w1l,
        b1, nullptr, (__nv_bfloat16*)p_f1h, (__nv_bfloat16*)p_f1l, FCDIM, POOLDIM);
    mma_fc_kernel<0><<<grid, 256, GEMM_SMEM>>>(
        (const __nv_bfloat16*)p_f1h, (const __nv_bfloat16*)p_f1l,
        (const __nv_bfloat16*)p_w2h, (const __nv_bfloat16*)p_w2l,
        b2, (float*)p_f7, nullptr, nullptr, FCDIM, FCDIM);

    head_kernel<<<NROI / 2, 256>>>(bloc, bsc);
    post_kernel<<<(NROI + 255) / 256, 256>>>(rois, out);
    nms_kernel<<<10, NROI>>>(out);
}

// round 6
// speedup vs baseline: 3.2069x; 1.0124x over previous
#include <cuda_runtime.h>
#include <cuda_bf16.h>
#include <math.h>
#include <stdint.h>

#define NROI 512
#define NCH 512
#define HF 37
#define WF 50
#define NCLS 11
#define POOLDIM 25088   // NCH * 7 * 7
#define FCDIM 4096

// ---------------- scratch (device globals; no allocation allowed) ----------
__device__ __nv_bfloat16 g_poolh[(size_t)NROI * POOLDIM];
__device__ __nv_bfloat16 g_pooll[(size_t)NROI * POOLDIM];
__device__ __nv_bfloat16 g_W1h[(size_t)POOLDIM * FCDIM];
__device__ __nv_bfloat16 g_W1l[(size_t)POOLDIM * FCDIM];
__device__ __nv_bfloat16 g_W2h[(size_t)FCDIM * FCDIM];
__device__ __nv_bfloat16 g_W2l[(size_t)FCDIM * FCDIM];
__device__ __nv_bfloat16 g_fc1h[(size_t)NROI * FCDIM];
__device__ __nv_bfloat16 g_fc1l[(size_t)NROI * FCDIM];
__device__ float g_fc7[(size_t)NROI * FCDIM];
__device__ float g_Wt[55 * FCDIM];
__device__ float g_ls[NROI * 55];
__device__ float g_bbox[NROI * 44];
__device__ float g_prob[NROI * 11];

__device__ __forceinline__ float neg_inf() { return __int_as_float(0xff800000); }
__device__ __forceinline__ float pos_inf() { return __int_as_float(0x7f800000); }

// ========================= PTX helpers (baseline ISA only) =================
__device__ __forceinline__ uint32_t smem_u32(const void* p) {
    uint32_t a;
    asm("{ .reg .u64 t; cvta.to.shared.u64 t, %1; cvt.u32.u64 %0, t; }" : "=r"(a) : "l"(p));
    return a;
}
__device__ __forceinline__ uint32_t pack_bf16x2(float lo, float hi) {
    uint32_t r;
    asm("cvt.rn.bf16x2.f32 %0, %1, %2;" : "=r"(r) : "f"(hi), "f"(lo));
    return r;
}

#define LDM_X4(r, a) \
    asm volatile("ldmatrix.sync.aligned.m8n8.x4.shared.b16 {%0,%1,%2,%3}, [%4];" \
        : "=r"((r)[0]), "=r"((r)[1]), "=r"((r)[2]), "=r"((r)[3]) : "r"(a))
#define LDM_X4T(r, a) \
    asm volatile("ldmatrix.sync.aligned.m8n8.x4.trans.shared.b16 {%0,%1,%2,%3}, [%4];" \
        : "=r"((r)[0]), "=r"((r)[1]), "=r"((r)[2]), "=r"((r)[3]) : "r"(a))

__device__ __forceinline__ void mma16816(float* c, const uint32_t* a, uint32_t b0, uint32_t b1) {
    asm volatile(
        "mma.sync.aligned.m16n8k16.row.col.f32.bf16.bf16.f32 "
        "{%0,%1,%2,%3}, {%4,%5,%6,%7}, {%8,%9}, {%0,%1,%2,%3};"
        : "+f"(c[0]), "+f"(c[1]), "+f"(c[2]), "+f"(c[3])
        : "r"(a[0]), "r"(a[1]), "r"(a[2]), "r"(a[3]), "r"(b0), "r"(b1));
}

#define CP16(dst, src) \
    asm volatile("cp.async.cg.shared.global [%0], [%1], 16;" :: "r"(dst), "l"(src))
#define CP_COMMIT() asm volatile("cp.async.commit_group;" ::: "memory")
#define CP_WAIT0() asm volatile("cp.async.wait_group 0;" ::: "memory")
#define CP_WAIT1() asm volatile("cp.async.wait_group 1;" ::: "memory")

// ========================= split-bf16 HMMA GEMM ============================
// C = relu(A*B + bias); A MxK, B KxN (pre-split bf16 hi/lo), 3-pass hh+hl+lh.
// Tile 128x128x32, 256 threads (8 warps of 64x32), 3-stage cp.async pipeline.
#define ST_AHI 0
#define ST_ALO 8192
#define ST_BHI 16384
#define ST_BLO 24576
#define STAGE_SZ 32768
#define NSTAGE 3
#define GEMM_SMEM (NSTAGE * STAGE_SZ)

__device__ __forceinline__ uint32_t aoff(int m, int k) {
    return (uint32_t)(m * 64 + ((((k >> 3) ^ ((m >> 1) ^ (m >> 3))) & 3) << 4) + (k & 7) * 2);
}
__device__ __forceinline__ uint32_t boff(int k, int n) {
    return (uint32_t)(k * 256 + ((((n >> 3) ^ (k & 7)) & 15) << 4) + (n & 7) * 2);
}

// OUT: 0 = fp32 out (Cf), 1 = split bf16 out (Ch, Cl)
template <int OUT>
__global__ void __launch_bounds__(256, 1)
mma_fc_kernel(const __nv_bfloat16* __restrict__ Ah, const __nv_bfloat16* __restrict__ Al,
              const __nv_bfloat16* __restrict__ Bh, const __nv_bfloat16* __restrict__ Bl,
              const float* __restrict__ bias, float* __restrict__ Cf,
              __nv_bfloat16* __restrict__ Ch, __nv_bfloat16* __restrict__ Cl,
              int N, int K) {
    extern __shared__ char smem[];
    uint32_t sbase = smem_u32(smem);
    const int t = threadIdx.x;
    const int lane = t & 31;
    const int wid = t >> 5;
    const int wy = wid & 1;
    const int wx = wid >> 1;
    const int m0 = blockIdx.y * 128;
    const int n0 = blockIdx.x * 128;

    const int am = t >> 1;
    const int ak = (t & 1) * 16;
    const int bk = t >> 3;
    const int bn = (t & 7) * 16;

    const int nit = K / 32;

    // precomputed per-thread staging addresses (offsets within a stage)
    const uint32_t oA0 = ST_AHI + aoff(am, ak);
    const uint32_t oA1 = ST_AHI + aoff(am, ak + 8);
    const uint32_t oB0 = ST_BHI + boff(bk, bn);
    const uint32_t oB1 = ST_BHI + boff(bk, bn + 8);

    float acc[4][4][4];
    #pragma unroll
    for (int i = 0; i < 4; i++)
        #pragma unroll
        for (int j = 0; j < 4; j++)
            #pragma unroll
            for (int e = 0; e < 4; e++) acc[i][j][e] = 0.0f;

#define ISSUE(stg, kg) do {                                                    \
        uint32_t s_ = sbase + (uint32_t)(stg) * STAGE_SZ;                      \
        const __nv_bfloat16* ah_ = Ah + (size_t)(m0 + am) * K + (kg) + ak;     \
        const __nv_bfloat16* al_ = Al + (size_t)(m0 + am) * K + (kg) + ak;     \
        CP16(s_ + oA0, ah_);                                                   \
        CP16(s_ + oA1, ah_ + 8);                                               \
        CP16(s_ + oA0 + (ST_ALO - ST_AHI), al_);                               \
        CP16(s_ + oA1 + (ST_ALO - ST_AHI), al_ + 8);                           \
        const __nv_bfloat16* bh_ = Bh + (size_t)((kg) + bk) * N + n0 + bn;     \
        const __nv_bfloat16* bl_ = Bl + (size_t)((kg) + bk) * N + n0 + bn;     \
        CP16(s_ + oB0, bh_);                                                   \
        CP16(s_ + oB1, bh_ + 8);                                               \
        CP16(s_ + oB0 + (ST_BLO - ST_BHI), bl_);                               \
        CP16(s_ + oB1 + (ST_BLO - ST_BHI), bl_ + 8);                           \
        CP_COMMIT();                                                           \
    } while (0)

    ISSUE(0, 0);
    ISSUE(1, 32);

    const int arow_l = lane & 15;
    const int khalf = (lane >> 4) << 3;

    int cur = 0, nxt = 2;   // stage being computed / stage to fill
    for (int it = 0; it < nit; it++) {
        if (it == nit - 1) { CP_WAIT0(); } else { CP_WAIT1(); }
        __syncthreads();
        if (it + 2 < nit) {
            ISSUE(nxt, (it + 2) * 32);
            if (++nxt == NSTAGE) nxt = 0;
        }

        uint32_t sA_hi = sbase + (uint32_t)cur * STAGE_SZ + ST_AHI;
        uint32_t sA_lo = sA_hi + (ST_ALO - ST_AHI);
        uint32_t sB_hi = sbase + (uint32_t)cur * STAGE_SZ + ST_BHI;
        uint32_t sB_lo = sB_hi + (ST_BLO - ST_BHI);
        if (++cur == NSTAGE) cur = 0;

        #pragma unroll
        for (int ks = 0; ks < 2; ks++) {
            const int k0 = ks * 16;
            uint32_t ah[4][4], al[4][4], bh[2][4], bl[2][4];
            #pragma unroll
            for (int mi = 0; mi < 4; mi++) {
                int mrow = wy * 64 + mi * 16 + arow_l;
                uint32_t oa = aoff(mrow, k0 + khalf);
                LDM_X4(ah[mi], sA_hi + oa);
                LDM_X4(al[mi], sA_lo + oa);
            }
            #pragma unroll
            for (int nt = 0; nt < 2; nt++) {
                int krow = k0 + (lane & 15);
                int ncol = wx * 32 + nt * 16 + khalf;
                uint32_t ob = boff(krow, ncol);
                LDM_X4T(bh[nt], sB_hi + ob);
                LDM_X4T(bl[nt], sB_lo + ob);
            }
            #pragma unroll
            for (int mi = 0; mi < 4; mi++) {
                #pragma unroll
                for (int ni = 0; ni < 4; ni++) {
                    int nt = ni >> 1;
                    int o = (ni & 1) * 2;
                    mma16816(acc[mi][ni], ah[mi], bh[nt][o], bh[nt][o + 1]);
                    mma16816(acc[mi][ni], ah[mi], bl[nt][o], bl[nt][o + 1]);
                    mma16816(acc[mi][ni], al[mi], bh[nt][o], bh[nt][o + 1]);
                }
            }
        }
    }

    // ---- epilogue: bias + relu + store ----
    #pragma unroll
    for (int mi = 0; mi < 4; mi++) {
        int mrow = m0 + wy * 64 + mi * 16 + (lane >> 2);
        #pragma unroll
        for (int ni = 0; ni < 4; ni++) {
            int ncol = n0 + wx * 32 + ni * 8 + (lane & 3) * 2;
            float bb0 = bias[ncol], bb1 = bias[ncol + 1];
            float v0 = fmaxf(acc[mi][ni][0] + bb0, 0.0f);
            float v1 = fmaxf(acc[mi][ni][1] + bb1, 0.0f);
            float v2 = fmaxf(acc[mi][ni][2] + bb0, 0.0f);
            float v3 = fmaxf(acc[mi][ni][3] + bb1, 0.0f);
            if (OUT == 0) {
                *(float2*)(Cf + (size_t)mrow * N + ncol)       = make_float2(v0, v1);
                *(float2*)(Cf + (size_t)(mrow + 8) * N + ncol) = make_float2(v2, v3);
            } else {
                uint32_t h01 = pack_bf16x2(v0, v1);
                uint32_t l01 = pack_bf16x2(v0 - __uint_as_float(h01 << 16),
                                           v1 - __uint_as_float(h01 & 0xffff0000u));
                uint32_t h23 = pack_bf16x2(v2, v3);
                uint32_t l23 = pack_bf16x2(v2 - __uint_as_float(h23 << 16),
                                           v3 - __uint_as_float(h23 & 0xffff0000u));
                *(uint32_t*)(Ch + (size_t)mrow * N + ncol)       = h01;
                *(uint32_t*)(Cl + (size_t)mrow * N + ncol)       = l01;
                *(uint32_t*)(Ch + (size_t)(mrow + 8) * N + ncol) = h23;
                *(uint32_t*)(Cl + (size_t)(mrow + 8) * N + ncol) = l23;
            }
        }
    }
#undef ISSUE
}

// ---------------- 0. fp32 -> bf16 hi/lo split (streaming) -------------------
__global__ void split_kernel(const float* __restrict__ src,
                             __nv_bfloat16* __restrict__ hi,
                             __nv_bfloat16* __restrict__ lo, size_t n4) {
    size_t stride = (size_t)gridDim.x * blockDim.x;
    for (size_t i = (size_t)blockIdx.x * blockDim.x + threadIdx.x; i < n4; i += stride) {
        float4 v = ((const float4*)src)[i];
        uint32_t h0 = pack_bf16x2(v.x, v.y);
        uint32_t h1 = pack_bf16x2(v.z, v.w);
        uint32_t l0 = pack_bf16x2(v.x - __uint_as_float(h0 << 16),
                                  v.y - __uint_as_float(h0 & 0xffff0000u));
        uint32_t l1 = pack_bf16x2(v.z - __uint_as_float(h1 << 16),
                                  v.w - __uint_as_float(h1 & 0xffff0000u));
        ((uint2*)hi)[i] = make_uint2(h0, h1);
        ((uint2*)lo)[i] = make_uint2(l0, l1);
    }
}

// ---------------- 1. ROI max-pool (emits bf16 hi/lo directly) ---------------
__global__ void roipool_kernel(const float* __restrict__ feat,
                               const float* __restrict__ rois,
                               const int* __restrict__ roi_idx) {
    int r = blockIdx.x;
    __shared__ int hs[7], he[7], ws[7], we[7];
    if (threadIdx.x == 0) {
        const float RECIP7 = 1.0f / 7.0f;   // matches XLA's x/7 -> x*recip rewrite
        float y1 = rois[r * 4 + 0], x1 = rois[r * 4 + 1];
        float y2 = rois[r * 4 + 2], x2 = rois[r * 4 + 3];
        float sw = rintf(x1 * 0.0625f);
        float ew = rintf(x2 * 0.0625f);
        float sh = rintf(y1 * 0.0625f);
        float eh = rintf(y2 * 0.0625f);
        float rw = fmaxf(ew - sw + 1.0f, 1.0f);
        float rh = fmaxf(eh - sh + 1.0f, 1.0f);
        #pragma unroll
        for (int p = 0; p < 7; p++) {
            float fp = (float)p;
            float h0 = floorf(__fmul_rn(fp * rh, RECIP7)) + sh;
            float h1 = ceilf(__fmul_rn((fp + 1.0f) * rh, RECIP7)) + sh;
            float w0 = floorf(__fmul_rn(fp * rw, RECIP7)) + sw;
            float w1 = ceilf(__fmul_rn((fp + 1.0f) * rw, RECIP7)) + sw;
            hs[p] = (int)fminf(fmaxf(h0, 0.0f), (float)HF);
            he[p] = (int)fminf(fmaxf(h1, 0.0f), (float)HF);
            ws[p] = (int)fminf(fmaxf(w0, 0.0f), (float)WF);
            we[p] = (int)fminf(fmaxf(w1, 0.0f), (float)WF);
        }
    }
    __syncthreads();
    int b = roi_idx[r];
    const float* f = feat + (size_t)b * NCH * HF * WF;
    for (int idx = threadIdx.x; idx < POOLDIM; idx += blockDim.x) {
        int c = idx / 49;
        int rem = idx - c * 49;
        int ph = rem / 7, pw = rem - (rem / 7) * 7;
        int h0 = hs[ph], h1 = he[ph], w0 = ws[pw], w1 = we[pw];
        float m = 0.0f;
        if (h1 > h0 && w1 > w0) {
            m = neg_inf();
            const float* fc_ = f + (size_t)c * (HF * WF);
            for (int y = h0; y < h1; y++)
                for (int x = w0; x < w1; x++)
                    m = fmaxf(m, fc_[y * WF + x]);
        }
        __nv_bfloat16 hb = __float2bfloat16(m);
        g_poolh[(size_t)r * POOLDIM + idx] = hb;
        g_pooll[(size_t)r * POOLDIM + idx] = __float2bfloat16(m - __bfloat162float(hb));
    }
}

// ---------------- 2. head W transpose: g_Wt[55][4096] ----------------------
__global__ void prep_head_kernel(const float* __restrict__ Wloc,
                                 const float* __restrict__ Wsc) {
    int stride = gridDim.x * blockDim.x;
    for (int i = blockIdx.x * blockDim.x + threadIdx.x; i < 55 * FCDIM; i += stride) {
        int col = i >> 12;
        int k = i & (FCDIM - 1);
        g_Wt[i] = (col < 44) ? Wloc[(size_t)k * 44 + col] : Wsc[(size_t)k * 11 + (col - 44)];
    }
}

// ---------------- 3. heads: 2 ROIs per block, warp-per-output --------------
__global__ void __launch_bounds__(256) head_kernel(const float* __restrict__ bloc,
                                                   const float* __restrict__ bsc) {
    __shared__ float4 Fs[2][FCDIM / 4];
    int r0 = blockIdx.x * 2;
    int t = threadIdx.x;
    for (int i = t; i < 2 * (FCDIM / 4); i += 256) {
        int ri = i >> 10, kk = i & 1023;
        Fs[ri][kk] = ((const float4*)g_fc7)[(size_t)(r0 + ri) * (FCDIM / 4) + kk];
    }
    __syncthreads();
    int w = t >> 5, lane = t & 31;
    for (int o = w; o < 110; o += 8) {
        int roi = (o >= 55) ? 1 : 0;
        int col = o - roi * 55;
        const float4* wp = (const float4*)(g_Wt + col * FCDIM);
        float acc = 0.0f;
        for (int kb = lane; kb < FCDIM / 4; kb += 32) {
            float4 f = Fs[roi][kb];
            float4 v = wp[kb];
            acc = fmaf(f.x, v.x, acc);
            acc = fmaf(f.y, v.y, acc);
            acc = fmaf(f.z, v.z, acc);
            acc = fmaf(f.w, v.w, acc);
        }
        #pragma unroll
        for (int of = 16; of > 0; of >>= 1) acc += __shfl_xor_sync(0xffffffffu, acc, of);
        if (lane == 0) {
            float bb = (col < 44) ? bloc[col] : bsc[col - 44];
            g_ls[(r0 + roi) * 55 + col] = acc + bb;
        }
    }
}

// ---------------- 4. bbox decode + clip + softmax ---------------------------
__global__ void post_kernel(const float* __restrict__ rois, float* __restrict__ out) {
    int r = blockIdx.x * blockDim.x + threadIdx.x;
    if (r >= NROI) return;
    float y1 = rois[r * 4 + 0], x1 = rois[r * 4 + 1];
    float y2 = rois[r * 4 + 2], x2 = rois[r * 4 + 3];
    float sh_ = y2 - y1, sw_ = x2 - x1;
    float cy = y1 + 0.5f * sh_, cx = x1 + 0.5f * sw_;
    #pragma unroll
    for (int c = 0; c < NCLS; c++) {
        float dy = g_ls[r * 55 + c * 4 + 0] * 0.1f;
        float dx = g_ls[r * 55 + c * 4 + 1] * 0.1f;
        float dh = g_ls[r * 55 + c * 4 + 2] * 0.2f;
        float dw = g_ls[r * 55 + c * 4 + 3] * 0.2f;
        float ncy = dy * sh_ + cy;
        float ncx = dx * sw_ + cx;
        float nh = expf(dh) * sh_;
        float nw = expf(dw) * sw_;
        float by1 = fminf(fmaxf(ncy - 0.5f * nh, 0.0f), 600.0f);
        float bx1 = fminf(fmaxf(ncx - 0.5f * nw, 0.0f), 800.0f);
        float by2 = fminf(fmaxf(ncy + 0.5f * nh, 0.0f), 600.0f);
        float bx2 = fminf(fmaxf(ncx + 0.5f * nw, 0.0f), 800.0f);
        g_bbox[r * 44 + c * 4 + 0] = by1;
        g_bbox[r * 44 + c * 4 + 1] = bx1;
        g_bbox[r * 44 + c * 4 + 2] = by2;
        g_bbox[r * 44 + c * 4 + 3] = bx2;
        out[r * 44 + c * 4 + 0] = by1;
        out[r * 44 + c * 4 + 1] = bx1;
        out[r * 44 + c * 4 + 2] = by2;
        out[r * 44 + c * 4 + 3] = bx2;
    }
    float sc[NCLS];
    float mx = neg_inf();
    #pragma unroll
    for (int c = 0; c < NCLS; c++) {
        sc[c] = g_ls[r * 55 + 44 + c];
        mx = fmaxf(mx, sc[c]);
    }
    float sum = 0.0f;
    #pragma unroll
    for (int c = 0; c < NCLS; c++) { sc[c] = expf(sc[c] - mx); sum += sc[c]; }
    #pragma unroll
    for (int c = 0; c < NCLS; c++) {
        float p = sc[c] / sum;
        g_prob[r * 11 + c] = p;
        out[NROI * 44 + r * 11 + c] = p;
    }
}

// ---------------- 5. per-class NMS ------------------------------------------
__global__ void __launch_bounds__(512) nms_kernel(float* __restrict__ out) {
    int cls = blockIdx.x + 1;
    int j = threadIdx.x;
    __shared__ float key[NROI];
    __shared__ int order[NROI];
    __shared__ float4 sb[NROI];
    __shared__ unsigned char keep[NROI];

    float s = g_prob[j * 11 + cls];
    bool valid = s > 0.05f;
    float kj = valid ? -s : pos_inf();
    key[j] = kj;
    __syncthreads();
    int rank = 0;
    for (int i = 0; i < NROI; i++) {
        float ki = key[i];
        rank += (ki < kj) || (ki == kj && i < j);
    }
    order[rank] = j;
    __syncthreads();
    int src = order[j];
    float4 box = *(const float4*)&g_bbox[src * 44 + cls * 4];
    sb[j] = box;
    keep[j] = (g_prob[src * 11 + cls] > 0.05f) ? 1 : 0;
    __syncthreads();

    float areaJ = (box.z - box.x) * (box.w - box.y);
    for (int i = 0; i < NROI - 1; i++) {
        if (keep[i] && j > i && keep[j]) {
            float4 bi = sb[i];
            float ty_ = fmaxf(box.x, bi.x);
            float tx_ = fmaxf(box.y, bi.y);
            float by_ = fminf(box.z, bi.z);
            float bx_ = fminf(box.w, bi.w);
            float ih = fmaxf(by_ - ty_, 0.0f);
            float iw = fmaxf(bx_ - tx_, 0.0f);
            float inter = ih * iw;
            float areaI = (bi.z - bi.x) * (bi.w - bi.y);
            float iou = inter / (areaJ + areaI - inter);
            if (iou > 0.3f) keep[j] = 0;
        }
        __syncthreads();
    }
    out[NROI * 44 + NROI * 11 + blockIdx.x * NROI + src] = keep[j] ? 1.0f : 0.0f;
}

// ---------------- launch ----------------------------------------------------
extern "C" void kernel_launch(void* const* d_in, const int* in_sizes, int n_in,
                              void* d_out, int out_size) {
    (void)in_sizes; (void)n_in; (void)out_size;
    const float* h    = (const float*)d_in[0];
    const float* rois = (const float*)d_in[1];
    const int*   ridx = (const int*)d_in[2];
    const float* W1   = (const float*)d_in[3];
    const float* b1   = (const float*)d_in[4];
    const float* W2   = (const float*)d_in[5];
    const float* b2   = (const float*)d_in[6];
    const float* Wloc = (const float*)d_in[7];
    const float* bloc = (const float*)d_in[8];
    const float* Wsc  = (const float*)d_in[9];
    const float* bsc  = (const float*)d_in[10];
    float* out = (float*)d_out;

    void *p_ph, *p_pl, *p_w1h, *p_w1l, *p_w2h, *p_w2l, *p_f1h, *p_f1l, *p_f7;
    cudaGetSymbolAddress(&p_ph, g_poolh);
    cudaGetSymbolAddress(&p_pl, g_pooll);
    cudaGetSymbolAddress(&p_w1h, g_W1h);
    cudaGetSymbolAddress(&p_w1l, g_W1l);
    cudaGetSymbolAddress(&p_w2h, g_W2h);
    cudaGetSymbolAddress(&p_w2l, g_W2l);
    cudaGetSymbolAddress(&p_f1h, g_fc1h);
    cudaGetSymbolAddress(&p_f1l, g_fc1l);
    cudaGetSymbolAddress(&p_f7, g_fc7);

    cudaFuncSetAttribute(mma_fc_kernel<0>,
                         cudaFuncAttributeMaxDynamicSharedMemorySize, GEMM_SMEM);
    cudaFuncSetAttribute(mma_fc_kernel<1>,
                         cudaFuncAttributeMaxDynamicSharedMemorySize, GEMM_SMEM);

    // order matters for ncu (-s picks our launch index 3 => GEMM1 gets profiled)
    roipool_kernel<<<NROI, 256>>>(h, rois, ridx);                           // 0
    split_kernel<<<4096, 256>>>(W1, (__nv_bfloat16*)p_w1h, (__nv_bfloat16*)p_w1l,
                                (size_t)POOLDIM * FCDIM / 4);               // 1
    split_kernel<<<2048, 256>>>(W2, (__nv_bfloat16*)p_w2h, (__nv_bfloat16*)p_w2l,
                                (size_t)FCDIM * FCDIM / 4);                 // 2

    dim3 grid(FCDIM / 128, NROI / 128);   // (32, 4)
    mma_fc_kernel<1><<<grid, 256, GEMM_SMEM>>>(                             // 3 (profiled)
        (const __nv_bfloat16*)p_ph, (const __nv_bfloat16*)p_pl,
        (const __nv_bfloat16*)p_w1h, (const __nv_bfloat16*)p_w1l,
        b1, nullptr, (__nv_bfloat16*)p_f1h, (__nv_bfloat16*)p_f1l, FCDIM, POOLDIM);
    mma_fc_kernel<0><<<grid, 256, GEMM_SMEM>>>(                             // 4
        (const __nv_bfloat16*)p_f1h, (const __nv_bfloat16*)p_f1l,
        (const __nv_bfloat16*)p_w2h, (const __nv_bfloat16*)p_w2l,
        b2, (float*)p_f7, nullptr, nullptr, FCDIM, FCDIM);

    prep_head_kernel<<<256, 256>>>(Wloc, Wsc);                              // 5
    head_kernel<<<NROI / 2, 256>>>(bloc, bsc);                              // 6
    post_kernel<<<(NROI + 255) / 256, 256>>>(rois, out);                    // 7
    nms_kernel<<<10, NROI>>>(out);                                          // 8
}

// round 7
// speedup vs baseline: 3.8158x; 1.1899x over previous
#include <cuda_runtime.h>
#include <cuda_bf16.h>
#include <math.h>
#include <stdint.h>

#define NROI 512
#define NCH 512
#define HF 37
#define WF 50
#define NCLS 11
#define POOLDIM 25088   // NCH * 7 * 7
#define FCDIM 4096

// ---------------- scratch (device globals; no allocation allowed) ----------
__device__ __nv_bfloat16 g_poolh[(size_t)NROI * POOLDIM];
__device__ __nv_bfloat16 g_pooll[(size_t)NROI * POOLDIM];
__device__ __nv_bfloat16 g_W1h[(size_t)POOLDIM * FCDIM];
__device__ __nv_bfloat16 g_W1l[(size_t)POOLDIM * FCDIM];
__device__ __nv_bfloat16 g_W2h[(size_t)FCDIM * FCDIM];
__device__ __nv_bfloat16 g_W2l[(size_t)FCDIM * FCDIM];
__device__ __nv_bfloat16 g_fc1h[(size_t)NROI * FCDIM];
__device__ __nv_bfloat16 g_fc1l[(size_t)NROI * FCDIM];
__device__ float g_fc7[(size_t)NROI * FCDIM];
__device__ float g_Wt[55 * FCDIM];
__device__ float g_ls[NROI * 55];
__device__ float g_bbox[NROI * 44];
__device__ float g_prob[NROI * 11];

__device__ __forceinline__ float neg_inf() { return __int_as_float(0xff800000); }
__device__ __forceinline__ float pos_inf() { return __int_as_float(0x7f800000); }

// ========================= PTX helpers (baseline ISA only) =================
__device__ __forceinline__ uint32_t smem_u32(const void* p) {
    uint32_t a;
    asm("{ .reg .u64 t; cvta.to.shared.u64 t, %1; cvt.u32.u64 %0, t; }" : "=r"(a) : "l"(p));
    return a;
}
__device__ __forceinline__ uint32_t pack_bf16x2(float lo, float hi) {
    uint32_t r;
    asm("cvt.rn.bf16x2.f32 %0, %1, %2;" : "=r"(r) : "f"(hi), "f"(lo));
    return r;
}

#define LDM_X4(r, a) \
    asm volatile("ldmatrix.sync.aligned.m8n8.x4.shared.b16 {%0,%1,%2,%3}, [%4];" \
        : "=r"((r)[0]), "=r"((r)[1]), "=r"((r)[2]), "=r"((r)[3]) : "r"(a))
#define LDM_X4T(r, a) \
    asm volatile("ldmatrix.sync.aligned.m8n8.x4.trans.shared.b16 {%0,%1,%2,%3}, [%4];" \
        : "=r"((r)[0]), "=r"((r)[1]), "=r"((r)[2]), "=r"((r)[3]) : "r"(a))

__device__ __forceinline__ void mma16816(float* c, const uint32_t* a, uint32_t b0, uint32_t b1) {
    asm volatile(
        "mma.sync.aligned.m16n8k16.row.col.f32.bf16.bf16.f32 "
        "{%0,%1,%2,%3}, {%4,%5,%6,%7}, {%8,%9}, {%0,%1,%2,%3};"
        : "+f"(c[0]), "+f"(c[1]), "+f"(c[2]), "+f"(c[3])
        : "r"(a[0]), "r"(a[1]), "r"(a[2]), "r"(a[3]), "r"(b0), "r"(b1));
}

#define CP16(dst, src) \
    asm volatile("cp.async.cg.shared.global [%0], [%1], 16;" :: "r"(dst), "l"(src))
#define CP_COMMIT() asm volatile("cp.async.commit_group;" ::: "memory")
#define CP_WAIT0() asm volatile("cp.async.wait_group 0;" ::: "memory")
#define CP_WAIT1() asm volatile("cp.async.wait_group 1;" ::: "memory")
#define CP_WAIT2() asm volatile("cp.async.wait_group 2;" ::: "memory")

// ========================= split-bf16 HMMA GEMM ============================
// C = relu(A*B + bias); A MxK, B KxN (pre-split bf16 hi/lo), 3-pass hh+hl+lh.
// Tile 128x128x32, 512 threads (16 warps, warp tile 32x32), 4-stage cp.async.
#define ST_AHI 0
#define ST_ALO 8192
#define ST_BHI 16384
#define ST_BLO 24576
#define STAGE_SZ 32768
#define NSTAGE 4
#define GEMM_SMEM (NSTAGE * STAGE_SZ)
#define GEMM_THREADS 512

__device__ __forceinline__ uint32_t aoff(int m, int k) {
    return (uint32_t)(m * 64 + ((((k >> 3) ^ ((m >> 1) ^ (m >> 3))) & 3) << 4) + (k & 7) * 2);
}
__device__ __forceinline__ uint32_t boff(int k, int n) {
    return (uint32_t)(k * 256 + ((((n >> 3) ^ (k & 7)) & 15) << 4) + (n & 7) * 2);
}

// OUT: 0 = fp32 out (Cf), 1 = split bf16 out (Ch, Cl)
template <int OUT>
__global__ void __launch_bounds__(GEMM_THREADS, 1)
mma_fc_kernel(const __nv_bfloat16* __restrict__ Ah, const __nv_bfloat16* __restrict__ Al,
              const __nv_bfloat16* __restrict__ Bh, const __nv_bfloat16* __restrict__ Bl,
              const float* __restrict__ bias, float* __restrict__ Cf,
              __nv_bfloat16* __restrict__ Ch, __nv_bfloat16* __restrict__ Cl,
              int N, int K) {
    extern __shared__ char smem[];
    uint32_t sbase = smem_u32(smem);
    const int t = threadIdx.x;
    const int lane = t & 31;
    const int wid = t >> 5;
    const int wy = wid & 3;          // 4 warp-rows of 32
    const int wx = wid >> 2;         // 4 warp-cols of 32
    const int m0 = blockIdx.y * 128;
    const int n0 = blockIdx.x * 128;

    // staging indices (512 threads: 4x CP16 each)
    const int am = t >> 2;           // 0..127
    const int ak = (t & 3) * 8;      // 0,8,16,24
    const int bk = t >> 4;           // 0..31
    const int bn = (t & 15) * 8;     // 0..120

    const uint32_t oA = ST_AHI + aoff(am, ak);
    const uint32_t oB = ST_BHI + boff(bk, bn);

    const int nit = K / 32;

    float acc[2][4][4];
    #pragma unroll
    for (int i = 0; i < 2; i++)
        #pragma unroll
        for (int j = 0; j < 4; j++)
            #pragma unroll
            for (int e = 0; e < 4; e++) acc[i][j][e] = 0.0f;

#define ISSUE(stg, kg) do {                                                    \
        uint32_t s_ = sbase + (uint32_t)(stg) * STAGE_SZ;                      \
        const __nv_bfloat16* ah_ = Ah + (size_t)(m0 + am) * K + (kg) + ak;     \
        const __nv_bfloat16* al_ = Al + (size_t)(m0 + am) * K + (kg) + ak;     \
        CP16(s_ + oA, ah_);                                                    \
        CP16(s_ + oA + (ST_ALO - ST_AHI), al_);                                \
        const __nv_bfloat16* bh_ = Bh + (size_t)((kg) + bk) * N + n0 + bn;     \
        const __nv_bfloat16* bl_ = Bl + (size_t)((kg) + bk) * N + n0 + bn;     \
        CP16(s_ + oB, bh_);                                                    \
        CP16(s_ + oB + (ST_BLO - ST_BHI), bl_);                                \
        CP_COMMIT();                                                           \
    } while (0)

    ISSUE(0, 0);
    ISSUE(1, 32);
    ISSUE(2, 64);

    const int arow_l = lane & 15;
    const int khalf = (lane >> 4) << 3;

    int cur = 0, nxt = 3;
    for (int it = 0; it < nit; it++) {
        if (it < nit - 2)      { CP_WAIT2(); }
        else if (it == nit - 2){ CP_WAIT1(); }
        else                   { CP_WAIT0(); }
        __syncthreads();
        if (it + 3 < nit) {
            ISSUE(nxt, (it + 3) * 32);
            if (++nxt == NSTAGE) nxt = 0;
        }

        uint32_t sA_hi = sbase + (uint32_t)cur * STAGE_SZ + ST_AHI;
        uint32_t sA_lo = sA_hi + (ST_ALO - ST_AHI);
        uint32_t sB_hi = sbase + (uint32_t)cur * STAGE_SZ + ST_BHI;
        uint32_t sB_lo = sB_hi + (ST_BLO - ST_BHI);
        if (++cur == NSTAGE) cur = 0;

        #pragma unroll
        for (int ks = 0; ks < 2; ks++) {
            const int k0 = ks * 16;
            uint32_t ah[2][4], al[2][4], bh[2][4], bl[2][4];
            #pragma unroll
            for (int mi = 0; mi < 2; mi++) {
                int mrow = wy * 32 + mi * 16 + arow_l;
                uint32_t oa = aoff(mrow, k0 + khalf);
                LDM_X4(ah[mi], sA_hi + oa);
                LDM_X4(al[mi], sA_lo + oa);
            }
            #pragma unroll
            for (int nt = 0; nt < 2; nt++) {
                int krow = k0 + (lane & 15);
                int ncol = wx * 32 + nt * 16 + khalf;
                uint32_t ob = boff(krow, ncol);
                LDM_X4T(bh[nt], sB_hi + ob);
                LDM_X4T(bl[nt], sB_lo + ob);
            }
            // pass-major ordering: RAW distance between MMAs on the same acc is 8
            #pragma unroll
            for (int mi = 0; mi < 2; mi++)
                #pragma unroll
                for (int ni = 0; ni < 4; ni++)
                    mma16816(acc[mi][ni], ah[mi], bh[ni >> 1][(ni & 1) * 2],
                             bh[ni >> 1][(ni & 1) * 2 + 1]);
            #pragma unroll
            for (int mi = 0; mi < 2; mi++)
                #pragma unroll
                for (int ni = 0; ni < 4; ni++)
                    mma16816(acc[mi][ni], ah[mi], bl[ni >> 1][(ni & 1) * 2],
                             bl[ni >> 1][(ni & 1) * 2 + 1]);
            #pragma unroll
            for (int mi = 0; mi < 2; mi++)
                #pragma unroll
                for (int ni = 0; ni < 4; ni++)
                    mma16816(acc[mi][ni], al[mi], bh[ni >> 1][(ni & 1) * 2],
                             bh[ni >> 1][(ni & 1) * 2 + 1]);
        }
    }

    // ---- epilogue: bias + relu + store ----
    #pragma unroll
    for (int mi = 0; mi < 2; mi++) {
        int mrow = m0 + wy * 32 + mi * 16 + (lane >> 2);
        #pragma unroll
        for (int ni = 0; ni < 4; ni++) {
            int ncol = n0 + wx * 32 + ni * 8 + (lane & 3) * 2;
            float bb0 = bias[ncol], bb1 = bias[ncol + 1];
            float v0 = fmaxf(acc[mi][ni][0] + bb0, 0.0f);
            float v1 = fmaxf(acc[mi][ni][1] + bb1, 0.0f);
            float v2 = fmaxf(acc[mi][ni][2] + bb0, 0.0f);
            float v3 = fmaxf(acc[mi][ni][3] + bb1, 0.0f);
            if (OUT == 0) {
                *(float2*)(Cf + (size_t)mrow * N + ncol)       = make_float2(v0, v1);
                *(float2*)(Cf + (size_t)(mrow + 8) * N + ncol) = make_float2(v2, v3);
            } else {
                uint32_t h01 = pack_bf16x2(v0, v1);
                uint32_t l01 = pack_bf16x2(v0 - __uint_as_float(h01 << 16),
                                           v1 - __uint_as_float(h01 & 0xffff0000u));
                uint32_t h23 = pack_bf16x2(v2, v3);
                uint32_t l23 = pack_bf16x2(v2 - __uint_as_float(h23 << 16),
                                           v3 - __uint_as_float(h23 & 0xffff0000u));
                *(uint32_t*)(Ch + (size_t)mrow * N + ncol)       = h01;
                *(uint32_t*)(Cl + (size_t)mrow * N + ncol)       = l01;
                *(uint32_t*)(Ch + (size_t)(mrow + 8) * N + ncol) = h23;
                *(uint32_t*)(Cl + (size_t)(mrow + 8) * N + ncol) = l23;
            }
        }
    }
#undef ISSUE
}

// ---------------- 0. fp32 -> bf16 hi/lo split (streaming) -------------------
__global__ void split_kernel(const float* __restrict__ src,
                             __nv_bfloat16* __restrict__ hi,
                             __nv_bfloat16* __restrict__ lo, size_t n4) {
    size_t stride = (size_t)gridDim.x * blockDim.x;
    for (size_t i = (size_t)blockIdx.x * blockDim.x + threadIdx.x; i < n4; i += stride) {
        float4 v = ((const float4*)src)[i];
        uint32_t h0 = pack_bf16x2(v.x, v.y);
        uint32_t h1 = pack_bf16x2(v.z, v.w);
        uint32_t l0 = pack_bf16x2(v.x - __uint_as_float(h0 << 16),
                                  v.y - __uint_as_float(h0 & 0xffff0000u));
        uint32_t l1 = pack_bf16x2(v.z - __uint_as_float(h1 << 16),
                                  v.w - __uint_as_float(h1 & 0xffff0000u));
        ((uint2*)hi)[i] = make_uint2(h0, h1);
        ((uint2*)lo)[i] = make_uint2(l0, l1);
    }
}

// ---------------- 1. ROI max-pool (emits bf16 hi/lo directly) ---------------
__global__ void __launch_bounds__(512) roipool_kernel(const float* __restrict__ feat,
                               const float* __restrict__ rois,
                               const int* __restrict__ roi_idx) {
    int r = blockIdx.x;
    __shared__ int hs[7], he[7], ws[7], we[7];
    if (threadIdx.x == 0) {
        const float RECIP7 = 1.0f / 7.0f;   // matches XLA's x/7 -> x*recip rewrite
        float y1 = rois[r * 4 + 0], x1 = rois[r * 4 + 1];
        float y2 = rois[r * 4 + 2], x2 = rois[r * 4 + 3];
        float sw = rintf(x1 * 0.0625f);
        float ew = rintf(x2 * 0.0625f);
        float sh = rintf(y1 * 0.0625f);
        float eh = rintf(y2 * 0.0625f);
        float rw = fmaxf(ew - sw + 1.0f, 1.0f);
        float rh = fmaxf(eh - sh + 1.0f, 1.0f);
        #pragma unroll
        for (int p = 0; p < 7; p++) {
            float fp = (float)p;
            float h0 = floorf(__fmul_rn(fp * rh, RECIP7)) + sh;
            float h1 = ceilf(__fmul_rn((fp + 1.0f) * rh, RECIP7)) + sh;
            float w0 = floorf(__fmul_rn(fp * rw, RECIP7)) + sw;
            float w1 = ceilf(__fmul_rn((fp + 1.0f) * rw, RECIP7)) + sw;
            hs[p] = (int)fminf(fmaxf(h0, 0.0f), (float)HF);
            he[p] = (int)fminf(fmaxf(h1, 0.0f), (float)HF);
            ws[p] = (int)fminf(fmaxf(w0, 0.0f), (float)WF);
            we[p] = (int)fminf(fmaxf(w1, 0.0f), (float)WF);
        }
    }
    __syncthreads();
    int b = roi_idx[r];
    const float* f = feat + (size_t)b * NCH * HF * WF;
    for (int idx = threadIdx.x; idx < POOLDIM; idx += blockDim.x) {
        int c = idx / 49;
        int rem = idx - c * 49;
        int ph = rem / 7, pw = rem - (rem / 7) * 7;
        int h0 = hs[ph], h1 = he[ph], w0 = ws[pw], w1 = we[pw];
        float m = 0.0f;
        if (h1 > h0 && w1 > w0) {
            m = neg_inf();
            const float* fc_ = f + (size_t)c * (HF * WF);
            for (int y = h0; y < h1; y++)
                for (int x = w0; x < w1; x++)
                    m = fmaxf(m, fc_[y * WF + x]);
        }
        __nv_bfloat16 hb = __float2bfloat16(m);
        g_poolh[(size_t)r * POOLDIM + idx] = hb;
        g_pooll[(size_t)r * POOLDIM + idx] = __float2bfloat16(m - __bfloat162float(hb));
    }
}

// ---------------- 2. head W transpose: g_Wt[55][4096] ----------------------
__global__ void prep_head_kernel(const float* __restrict__ Wloc,
                                 const float* __restrict__ Wsc) {
    int stride = gridDim.x * blockDim.x;
    for (int i = blockIdx.x * blockDim.x + threadIdx.x; i < 55 * FCDIM; i += stride) {
        int col = i >> 12;
        int k = i & (FCDIM - 1);
        g_Wt[i] = (col < 44) ? Wloc[(size_t)k * 44 + col] : Wsc[(size_t)k * 11 + (col - 44)];
    }
}

// ---------------- 3. heads: 2 ROIs per block, warp-per-output --------------
__global__ void __launch_bounds__(256) head_kernel(const float* __restrict__ bloc,
                                                   const float* __restrict__ bsc) {
    __shared__ float4 Fs[2][FCDIM / 4];
    int r0 = blockIdx.x * 2;
    int t = threadIdx.x;
    for (int i = t; i < 2 * (FCDIM / 4); i += 256) {
        int ri = i >> 10, kk = i & 1023;
        Fs[ri][kk] = ((const float4*)g_fc7)[(size_t)(r0 + ri) * (FCDIM / 4) + kk];
    }
    __syncthreads();
    int w = t >> 5, lane = t & 31;
    for (int o = w; o < 110; o += 8) {
        int roi = (o >= 55) ? 1 : 0;
        int col = o - roi * 55;
        const float4* wp = (const float4*)(g_Wt + col * FCDIM);
        float acc = 0.0f;
        for (int kb = lane; kb < FCDIM / 4; kb += 32) {
            float4 f = Fs[roi][kb];
            float4 v = wp[kb];
            acc = fmaf(f.x, v.x, acc);
            acc = fmaf(f.y, v.y, acc);
            acc = fmaf(f.z, v.z, acc);
            acc = fmaf(f.w, v.w, acc);
        }
        #pragma unroll
        for (int of = 16; of > 0; of >>= 1) acc += __shfl_xor_sync(0xffffffffu, acc, of);
        if (lane == 0) {
            float bb = (col < 44) ? bloc[col] : bsc[col - 44];
            g_ls[(r0 + roi) * 55 + col] = acc + bb;
        }
    }
}

// ---------------- 4. bbox decode + clip + softmax ---------------------------
__global__ void post_kernel(const float* __restrict__ rois, float* __restrict__ out) {
    int r = blockIdx.x * blockDim.x + threadIdx.x;
    if (r >= NROI) return;
    float y1 = rois[r * 4 + 0], x1 = rois[r * 4 + 1];
    float y2 = rois[r * 4 + 2], x2 = rois[r * 4 + 3];
    float sh_ = y2 - y1, sw_ = x2 - x1;
    float cy = y1 + 0.5f * sh_, cx = x1 + 0.5f * sw_;
    #pragma unroll
    for (int c = 0; c < NCLS; c++) {
        float dy = g_ls[r * 55 + c * 4 + 0] * 0.1f;
        float dx = g_ls[r * 55 + c * 4 + 1] * 0.1f;
        float dh = g_ls[r * 55 + c * 4 + 2] * 0.2f;
        float dw = g_ls[r * 55 + c * 4 + 3] * 0.2f;
        float ncy = dy * sh_ + cy;
        float ncx = dx * sw_ + cx;
        float nh = expf(dh) * sh_;
        float nw = expf(dw) * sw_;
        float by1 = fminf(fmaxf(ncy - 0.5f * nh, 0.0f), 600.0f);
        float bx1 = fminf(fmaxf(ncx - 0.5f * nw, 0.0f), 800.0f);
        float by2 = fminf(fmaxf(ncy + 0.5f * nh, 0.0f), 600.0f);
        float bx2 = fminf(fmaxf(ncx + 0.5f * nw, 0.0f), 800.0f);
        g_bbox[r * 44 + c * 4 + 0] = by1;
        g_bbox[r * 44 + c * 4 + 1] = bx1;
        g_bbox[r * 44 + c * 4 + 2] = by2;
        g_bbox[r * 44 + c * 4 + 3] = bx2;
        out[r * 44 + c * 4 + 0] = by1;
        out[r * 44 + c * 4 + 1] = bx1;
        out[r * 44 + c * 4 + 2] = by2;
        out[r * 44 + c * 4 + 3] = bx2;
    }
    float sc[NCLS];
    float mx = neg_inf();
    #pragma unroll
    for (int c = 0; c < NCLS; c++) {
        sc[c] = g_ls[r * 55 + 44 + c];
        mx = fmaxf(mx, sc[c]);
    }
    float sum = 0.0f;
    #pragma unroll
    for (int c = 0; c < NCLS; c++) { sc[c] = expf(sc[c] - mx); sum += sc[c]; }
    #pragma unroll
    for (int c = 0; c < NCLS; c++) {
        float p = sc[c] / sum;
        g_prob[r * 11 + c] = p;
        out[NROI * 44 + r * 11 + c] = p;
    }
}

// ---------------- 5. per-class NMS ------------------------------------------
__global__ void __launch_bounds__(512) nms_kernel(float* __restrict__ out) {
    int cls = blockIdx.x + 1;
    int j = threadIdx.x;
    __shared__ float key[NROI];
    __shared__ int order[NROI];
    __shared__ float4 sb[NROI];
    __shared__ unsigned char keep[NROI];

    float s = g_prob[j * 11 + cls];
    bool valid = s > 0.05f;
    float kj = valid ? -s : pos_inf();
    key[j] = kj;
    __syncthreads();
    int rank = 0;
    for (int i = 0; i < NROI; i++) {
        float ki = key[i];
        rank += (ki < kj) || (ki == kj && i < j);
    }
    order[rank] = j;
    __syncthreads();
    int src = order[j];
    float4 box = *(const float4*)&g_bbox[src * 44 + cls * 4];
    sb[j] = box;
    keep[j] = (g_prob[src * 11 + cls] > 0.05f) ? 1 : 0;
    __syncthreads();

    float areaJ = (box.z - box.x) * (box.w - box.y);
    for (int i = 0; i < NROI - 1; i++) {
        if (keep[i] && j > i && keep[j]) {
            float4 bi = sb[i];
            float ty_ = fmaxf(box.x, bi.x);
            float tx_ = fmaxf(box.y, bi.y);
            float by_ = fminf(box.z, bi.z);
            float bx_ = fminf(box.w, bi.w);
            float ih = fmaxf(by_ - ty_, 0.0f);
            float iw = fmaxf(bx_ - tx_, 0.0f);
            float inter = ih * iw;
            float areaI = (bi.z - bi.x) * (bi.w - bi.y);
            float iou = inter / (areaJ + areaI - inter);
            if (iou > 0.3f) keep[j] = 0;
        }
        __syncthreads();
    }
    out[NROI * 44 + NROI * 11 + blockIdx.x * NROI + src] = keep[j] ? 1.0f : 0.0f;
}

// ---------------- launch ----------------------------------------------------
extern "C" void kernel_launch(void* const* d_in, const int* in_sizes, int n_in,
                              void* d_out, int out_size) {
    (void)in_sizes; (void)n_in; (void)out_size;
    const float* h    = (const float*)d_in[0];
    const float* rois = (const float*)d_in[1];
    const int*   ridx = (const int*)d_in[2];
    const float* W1   = (const float*)d_in[3];
    const float* b1   = (const float*)d_in[4];
    const float* W2   = (const float*)d_in[5];
    const float* b2   = (const float*)d_in[6];
    const float* Wloc = (const float*)d_in[7];
    const float* bloc = (const float*)d_in[8];
    const float* Wsc  = (const float*)d_in[9];
    const float* bsc  = (const float*)d_in[10];
    float* out = (float*)d_out;

    void *p_ph, *p_pl, *p_w1h, *p_w1l, *p_w2h, *p_w2l, *p_f1h, *p_f1l, *p_f7;
    cudaGetSymbolAddress(&p_ph, g_poolh);
    cudaGetSymbolAddress(&p_pl, g_pooll);
    cudaGetSymbolAddress(&p_w1h, g_W1h);
    cudaGetSymbolAddress(&p_w1l, g_W1l);
    cudaGetSymbolAddress(&p_w2h, g_W2h);
    cudaGetSymbolAddress(&p_w2l, g_W2l);
    cudaGetSymbolAddress(&p_f1h, g_fc1h);
    cudaGetSymbolAddress(&p_f1l, g_fc1l);
    cudaGetSymbolAddress(&p_f7, g_fc7);

    cudaFuncSetAttribute(mma_fc_kernel<0>,
                         cudaFuncAttributeMaxDynamicSharedMemorySize, GEMM_SMEM);
    cudaFuncSetAttribute(mma_fc_kernel<1>,
                         cudaFuncAttributeMaxDynamicSharedMemorySize, GEMM_SMEM);

    // launch index 3 = GEMM1 (ncu profiles our 4th launch)
    roipool_kernel<<<NROI, 512>>>(h, rois, ridx);                           // 0
    split_kernel<<<4096, 256>>>(W1, (__nv_bfloat16*)p_w1h, (__nv_bfloat16*)p_w1l,
                                (size_t)POOLDIM * FCDIM / 4);               // 1
    split_kernel<<<2048, 256>>>(W2, (__nv_bfloat16*)p_w2h, (__nv_bfloat16*)p_w2l,
                                (size_t)FCDIM * FCDIM / 4);                 // 2

    dim3 grid(FCDIM / 128, NROI / 128);   // (32, 4)
    mma_fc_kernel<1><<<grid, GEMM_THREADS, GEMM_SMEM>>>(                    // 3 (profiled)
        (const __nv_bfloat16*)p_ph, (const __nv_bfloat16*)p_pl,
        (const __nv_bfloat16*)p_w1h, (const __nv_bfloat16*)p_w1l,
        b1, nullptr, (__nv_bfloat16*)p_f1h, (__nv_bfloat16*)p_f1l, FCDIM, POOLDIM);
    mma_fc_kernel<0><<<grid, GEMM_THREADS, GEMM_SMEM>>>(                    // 4
        (const __nv_bfloat16*)p_f1h, (const __nv_bfloat16*)p_f1l,
        (const __nv_bfloat16*)p_w2h, (const __nv_bfloat16*)p_w2l,
        b2, (float*)p_f7, nullptr, nullptr, FCDIM, FCDIM);

    prep_head_kernel<<<256, 256>>>(Wloc, Wsc);                              // 5
    head_kernel<<<NROI / 2, 256>>>(bloc, bsc);                              // 6
    post_kernel<<<(NROI + 255) / 256, 256>>>(rois, out);                    // 7
    nms_kernel<<<10, NROI>>>(out);                                          // 8
}